// round 10
// baseline (speedup 1.0000x reference)
#include <cuda_runtime.h>
#include <cuda_fp16.h>
#include <math.h>
#include <cstdint>

#define Bb   2048
#define Nn   64
#define Hh   256
#define MTOT (Bb*Nn)          // 131072

// ---------------- scratch (static device globals; no allocations) ----------
__device__ float g_hn  [MTOT*Hh];         // hidden after GRU cell (fp32)
__device__ float g_star[Bb*Hh];
__device__ float g_bias1[512];
// fp16 split activations / rounded weights
__device__ __half g_hH  [MTOT*256];
__device__ __half g_hL  [MTOT*256];       // epilogue-only (exact h reconstruction)
__device__ __half g_hioH[MTOT*512];
__device__ __half g_inpH[MTOT*512];
__device__ __half g_AH  [Bb*64*128];
__device__ __half g_AL  [Bb*64*128];
__device__ __half g_w1  [512*256];        // [c][k]: c<256 W_in, else W_out
__device__ __half g_wih [768*512];        // [n][k]
__device__ __half g_whh [768*256];

// ---------------- helpers ----------------------------------------------------
__device__ __forceinline__ uint32_t smem_u32(const void* p) {
    uint32_t a;
    asm("{ .reg .u64 t; cvta.to.shared.u64 t, %1; cvt.u32.u64 %0, t; }"
        : "=r"(a) : "l"(p));
    return a;
}
__device__ __forceinline__ void cp16(uint32_t dst, const void* src) {
    asm volatile("cp.async.cg.shared.global [%0], [%1], 16;"
                 :: "r"(dst), "l"(src) : "memory");
}
#define CP_COMMIT() asm volatile("cp.async.commit_group;" ::: "memory")
#define CP_WAIT(n)  asm volatile("cp.async.wait_group %0;" :: "n"(n) : "memory")

__device__ __forceinline__ void ldsm_x4(uint32_t& r0, uint32_t& r1,
                                        uint32_t& r2, uint32_t& r3,
                                        uint32_t addr) {
    asm volatile("ldmatrix.sync.aligned.m8n8.x4.shared.b16 {%0,%1,%2,%3}, [%4];"
                 : "=r"(r0), "=r"(r1), "=r"(r2), "=r"(r3) : "r"(addr));
}
__device__ __forceinline__ void ldsm_x4_t(uint32_t& r0, uint32_t& r1,
                                          uint32_t& r2, uint32_t& r3,
                                          uint32_t addr) {
    asm volatile("ldmatrix.sync.aligned.m8n8.x4.trans.shared.b16 {%0,%1,%2,%3}, [%4];"
                 : "=r"(r0), "=r"(r1), "=r"(r2), "=r"(r3) : "r"(addr));
}
__device__ __forceinline__ void mma_f16(float* d,
                                        uint32_t a0, uint32_t a1,
                                        uint32_t a2, uint32_t a3,
                                        uint32_t b0, uint32_t b1) {
    asm volatile(
        "mma.sync.aligned.m16n8k16.row.col.f32.f16.f16.f32 "
        "{%0,%1,%2,%3}, {%4,%5,%6,%7}, {%8,%9}, {%0,%1,%2,%3};"
        : "+f"(d[0]), "+f"(d[1]), "+f"(d[2]), "+f"(d[3])
        : "r"(a0), "r"(a1), "r"(a2), "r"(a3), "r"(b0), "r"(b1));
}
__device__ __forceinline__ void h_split(float v, __half& hi, __half& lo) {
    hi = __float2half_rn(v);
    lo = __float2half_rn(v - __half2float(hi));
}

// ---------------- setup -------------------------------------------------------
__global__ void setup_weights(const float* __restrict__ W_in,
                              const float* __restrict__ b_in,
                              const float* __restrict__ W_out,
                              const float* __restrict__ b_out,
                              const float* __restrict__ w_ih,
                              const float* __restrict__ w_hh) {
    int i = blockIdx.x * blockDim.x + threadIdx.x;
    if (i < 512) g_bias1[i] = (i < 256) ? b_in[i] : b_out[i-256];
    if (i < 512*256) {
        int c = i >> 8, k = i & 255;
        float v = (c < 256) ? W_in[c*256 + k] : W_out[(c-256)*256 + k];
        g_w1[i] = __float2half_rn(v);
    }
    if (i < 768*512) g_wih[i] = __float2half_rn(w_ih[i]);
    if (i < 768*256) g_whh[i] = __float2half_rn(w_hh[i]);
}

__global__ void setup_A(const float* __restrict__ A) {
    size_t n = (size_t)Bb*64*128;
    for (size_t i = blockIdx.x*(size_t)blockDim.x + threadIdx.x; i < n;
         i += (size_t)gridDim.x*blockDim.x) {
        __half hi, lo; h_split(A[i], hi, lo);
        g_AH[i] = hi; g_AL[i] = lo;
    }
}

// fused: split hidden into hH/hL + compute star (masked mean)
__global__ void __launch_bounds__(256) init_h(const float* __restrict__ hidden,
                                              const float* __restrict__ mask) {
    int b = blockIdx.x, t = threadIdx.x;
    float len = 0.f, acc = 0.f;
#pragma unroll 4
    for (int n = 0; n < 64; n++) {
        float mk = mask[b*64 + n];
        size_t idx = ((size_t)b*64 + n)*256 + t;
        float v = hidden[idx];
        __half hi, lo; h_split(v, hi, lo);
        g_hH[idx] = hi; g_hL[idx] = lo;
        acc += v * mk; len += mk;
    }
    g_star[(size_t)b*256 + t] = acc / len;
}

// ---------------- GEMM1 (fp16): hio = h @ [W_in^T|W_out^T] + bias ------------
#define G1_STAGE 27648   // A hi 18432 + B 9216
#define G1_SMEM  (2*G1_STAGE)

__device__ __forceinline__ void g1_load(uint32_t sbase, int st, int ch,
                                        int m0, int c0) {
    const int t = threadIdx.x;
    uint32_t sb = sbase + st*G1_STAGE;
    int koff = ch*64;
#pragma unroll
    for (int f = 0; f < 4; f++) {
        int u = f*256 + t; int row = u >> 3, seg = u & 7;
        cp16(sb + row*144 + seg*16,
             g_hH + (size_t)(m0+row)*256 + koff + seg*8);
    }
#pragma unroll
    for (int f = 0; f < 2; f++) {
        int u = f*256 + t; int row = u >> 3, seg = u & 7;
        cp16(sb + 18432 + row*144 + seg*16,
             g_w1 + (size_t)(c0+row)*256 + koff + seg*8);
    }
}

__global__ void __launch_bounds__(256, 2) gemm1_mma() {
    extern __shared__ __align__(16) char smem[];
    const int t = threadIdx.x, wid = t >> 5, lane = t & 31;
    const int c0 = blockIdx.x * 64, m0 = blockIdx.y * 128;
    uint32_t sbase = smem_u32(smem);
    float acc[8][4];
#pragma unroll
    for (int j = 0; j < 8; j++)
#pragma unroll
        for (int i = 0; i < 4; i++) acc[j][i] = 0.f;

    g1_load(sbase, 0, 0, m0, c0);
    CP_COMMIT();

    const uint32_t aRow0 = (wid*16 + (lane & 15))*144 + (lane >> 4)*16;
    const int midx = lane >> 3;
    const int trow = (midx >> 1)*8 + (lane & 7);
    const int kh   = (midx & 1)*16;

    for (int ch = 0; ch < 4; ch++) {
        if (ch + 1 < 4) {
            g1_load(sbase, (ch + 1) & 1, ch + 1, m0, c0);
            CP_COMMIT();
            CP_WAIT(1);
        } else {
            CP_WAIT(0);
        }
        __syncthreads();
        uint32_t sb = sbase + (ch & 1)*G1_STAGE;
        uint32_t aRow = sb + aRow0;
#pragma unroll
        for (int kt = 0; kt < 4; kt++) {
            uint32_t a0, a1, a2, a3;
            ldsm_x4(a0, a1, a2, a3, aRow + kt*32);
#pragma unroll
            for (int jj = 0; jj < 4; jj++) {
                uint32_t ba = sb + 18432 + (jj*16 + trow)*144 + kt*32 + kh;
                uint32_t b0, b1, b2, b3;
                ldsm_x4(b0, b1, b2, b3, ba);
                mma_f16(acc[2*jj],   a0, a1, a2, a3, b0, b1);
                mma_f16(acc[2*jj+1], a0, a1, a2, a3, b2, b3);
            }
        }
        __syncthreads();
    }
    const int r0 = m0 + wid*16 + (lane >> 2);
    const int cb = (lane & 3)*2;
#pragma unroll
    for (int j = 0; j < 8; j++) {
        int c = c0 + j*8 + cb;
        float2 bz = *(const float2*)&g_bias1[c];
#pragma unroll
        for (int hrow = 0; hrow < 2; hrow++) {
            int m = r0 + hrow*8;
            float v0 = acc[j][hrow*2]   + bz.x;
            float v1 = acc[j][hrow*2+1] + bz.y;
            *(__half2*)&g_hioH[(size_t)m*512 + c] =
                __halves2half2(__float2half_rn(v0), __float2half_rn(v1));
        }
    }
}

// ---------------- GEMM2 (fp16x2): inp = A_adj @ hio + bias --------------------
#define G2_A   0          // 2 planes x 64 x 144 = 18432
#define G2_B   18432      // 1 plane  x 64 x 528 = 33792
#define G2_SMEM 52224

__global__ void __launch_bounds__(256, 2) gemm2_mma(const float* __restrict__ b_iah,
                                                    const float* __restrict__ b_oah) {
    extern __shared__ __align__(16) char smem[];
    const int t = threadIdx.x, wid = t >> 5, lane = t & 31;
    const int b = blockIdx.x, half_ = blockIdx.y;
    uint32_t sbase = smem_u32(smem);
#pragma unroll
    for (int f = 0; f < 4; f++) {
        int u = f*256 + t; int pl = u >> 9, row = (u >> 3) & 63, seg = u & 7;
        const __half* src = pl ? g_AL : g_AH;
        cp16(sbase + G2_A + pl*9216 + row*144 + seg*16,
             src + (size_t)b*8192 + row*128 + half_*64 + seg*8);
    }
#pragma unroll
    for (int f = 0; f < 8; f++) {
        int u = f*256 + t; int row = u >> 5, seg = u & 31;
        cp16(sbase + G2_B + row*528 + seg*16,
             g_hioH + ((size_t)b*64 + row)*512 + half_*256 + seg*8);
    }
    CP_COMMIT(); CP_WAIT(0);
    __syncthreads();

    const int wr = wid >> 2, wc = wid & 3;
    float acc[2][8][4];
#pragma unroll
    for (int r = 0; r < 2; r++)
#pragma unroll
        for (int j = 0; j < 8; j++)
#pragma unroll
            for (int i = 0; i < 4; i++) acc[r][j][i] = 0.f;

    uint32_t aBase = sbase + G2_A + (wr*32 + (lane & 15))*144 + (lane >> 4)*16;
#pragma unroll
    for (int kt = 0; kt < 4; kt++) {
        uint32_t ah[2][4], al[2][4];
#pragma unroll
        for (int r = 0; r < 2; r++) {
            ldsm_x4(ah[r][0], ah[r][1], ah[r][2], ah[r][3],
                    aBase + r*2304 + kt*32);
            ldsm_x4(al[r][0], al[r][1], al[r][2], al[r][3],
                    aBase + 9216 + r*2304 + kt*32);
        }
#pragma unroll
        for (int jj = 0; jj < 4; jj++) {
            uint32_t ba = sbase + G2_B + (kt*16 + (lane & 15))*528 +
                          (wc*64 + jj*16 + (lane >> 4)*8)*2;
            uint32_t bh0, bh1, bh2, bh3;
            ldsm_x4_t(bh0, bh1, bh2, bh3, ba);
#pragma unroll
            for (int r = 0; r < 2; r++) {
                mma_f16(acc[r][jj*2],   ah[r][0], ah[r][1], ah[r][2], ah[r][3], bh0, bh1);
                mma_f16(acc[r][jj*2+1], ah[r][0], ah[r][1], ah[r][2], ah[r][3], bh2, bh3);
                mma_f16(acc[r][jj*2],   al[r][0], al[r][1], al[r][2], al[r][3], bh0, bh1);
                mma_f16(acc[r][jj*2+1], al[r][0], al[r][1], al[r][2], al[r][3], bh2, bh3);
            }
        }
    }
    const float* bias = half_ ? b_oah : b_iah;
#pragma unroll
    for (int r = 0; r < 2; r++) {
        int n = wr*32 + r*16 + (lane >> 2);
#pragma unroll
        for (int j = 0; j < 8; j++) {
            int col = wc*64 + j*8 + (lane & 3)*2;
#pragma unroll
            for (int hrow = 0; hrow < 2; hrow++) {
                int nn = n + hrow*8;
                float v0 = acc[r][j][hrow*2]   + bias[col];
                float v1 = acc[r][j][hrow*2+1] + bias[col+1];
                size_t o = ((size_t)b*64 + nn)*512 + half_*256 + col;
                *(__half2*)&g_inpH[o] =
                    __halves2half2(__float2half_rn(v0), __float2half_rn(v1));
            }
        }
    }
}

// ---------------- GEMM3 (A-resident): gates + fused GRU ------------------------
// One CTA = 128 rows x ALL 256 cols. A panel (inp 128x512 + h 128x256 fp16)
// resident in smem (row stride 1552B); loops 8 col-groups x 12 K-chunks,
// double-buffering only the B tile (96 rows x 144B).
#define G3A_STRIDE 1552
#define G3_BB     198656              // A: 128*1552
#define G3_BSTG   13824               // 96 x 144
#define G3_SMEM   (G3_BB + 2*G3_BSTG) // 226304

__device__ __forceinline__ void g3_loadB(uint32_t sbase, int bf, int it, int /*m0*/) {
    const int t = threadIdx.x;
    int cg = it / 12, ch = it % 12;
    uint32_t sb = sbase + G3_BB + bf*G3_BSTG;
    const __half* Bw; int ak, koff;
    if (ch < 8) { Bw = g_wih; ak = 512; koff = ch*64; }
    else        { Bw = g_whh; ak = 256; koff = (ch-8)*64; }
#pragma unroll
    for (int f = 0; f < 3; f++) {
        int u = f*256 + t; int row = u >> 3, seg = u & 7;
        int g = row >> 5, n = row & 31;
        cp16(sb + row*144 + seg*16,
             Bw + (size_t)(g*256 + cg*32 + n)*ak + koff + seg*8);
    }
}

__global__ void __launch_bounds__(256, 1) gemm3_mma(const float* __restrict__ b_ih,
                                                    const float* __restrict__ b_hh) {
    extern __shared__ __align__(16) char smem[];
    const int t = threadIdx.x, wid = t >> 5, lane = t & 31;
    const int m0 = blockIdx.x * 128;
    const int wr = wid & 3, wc = wid >> 2;
    uint32_t sbase = smem_u32(smem);

    // ---- load resident A panel: inp (64 segs/row) + h (32 segs/row) ----
#pragma unroll
    for (int f = 0; f < 32; f++) {
        int u = f*256 + t; int row = u >> 6, seg = u & 63;
        cp16(sbase + row*G3A_STRIDE + seg*16,
             g_inpH + (size_t)(m0+row)*512 + seg*8);
    }
#pragma unroll
    for (int f = 0; f < 16; f++) {
        int u = f*256 + t; int row = u >> 5, seg = u & 31;
        cp16(sbase + row*G3A_STRIDE + 1024 + seg*16,
             g_hH + (size_t)(m0+row)*256 + seg*8);
    }
    g3_loadB(sbase, 0, 0, m0);
    CP_COMMIT();

    const int midx = lane >> 3;
    const int trow = (midx >> 1)*8 + (lane & 7);
    const int kh   = (midx & 1)*16;
    const uint32_t aRow0 = sbase + (wr*32 + (lane & 15))*G3A_STRIDE +
                           (lane >> 4)*16;

    for (int cg = 0; cg < 8; cg++) {
        float acc[4][2][2][4];
#pragma unroll
        for (int p = 0; p < 4; p++)
#pragma unroll
            for (int r = 0; r < 2; r++)
#pragma unroll
                for (int cgi = 0; cgi < 2; cgi++)
#pragma unroll
                    for (int i = 0; i < 4; i++) acc[p][r][cgi][i] = 0.f;

        for (int ch = 0; ch < 12; ch++) {
            int it = cg*12 + ch;
            if (it + 1 < 96) {
                g3_loadB(sbase, (it + 1) & 1, it + 1, m0);
                CP_COMMIT();
                CP_WAIT(1);
            } else {
                CP_WAIT(0);
            }
            __syncthreads();
            uint32_t sbB = sbase + G3_BB + (it & 1)*G3_BSTG;
            uint32_t koff = (ch < 8) ? (uint32_t)(ch*128)
                                     : (uint32_t)(1024 + (ch-8)*128);
            const bool GH = (ch >= 8);
#pragma unroll
            for (int kt = 0; kt < 4; kt++) {
                uint32_t a[2][4];
#pragma unroll
                for (int r = 0; r < 2; r++)
                    ldsm_x4(a[r][0], a[r][1], a[r][2], a[r][3],
                            aRow0 + r*16*G3A_STRIDE + koff + kt*32);
#pragma unroll
                for (int g = 0; g < 3; g++) {
                    const int p = (!GH || g < 2) ? g : 3;
                    uint32_t b0, b1, b2, b3;
                    ldsm_x4(b0, b1, b2, b3,
                            sbB + (g*32 + wc*16 + trow)*144 + kt*32 + kh);
#pragma unroll
                    for (int r = 0; r < 2; r++) {
                        mma_f16(acc[p][r][0], a[r][0], a[r][1], a[r][2], a[r][3], b0, b1);
                        mma_f16(acc[p][r][1], a[r][0], a[r][1], a[r][2], a[r][3], b2, b3);
                    }
                }
            }
            __syncthreads();
        }

        // GRU epilogue for this col-group (h reconstructed exactly from hi/lo)
        const int c0 = cg * 32;
        const int rbase = m0 + wr*32 + (lane >> 2);
        const int cb = (lane & 3)*2;
#pragma unroll
        for (int r = 0; r < 2; r++) {
#pragma unroll
            for (int cgi = 0; cgi < 2; cgi++) {
                int cl = wc*16 + cgi*8 + cb;
                int c  = c0 + cl;
#pragma unroll
                for (int hrow = 0; hrow < 2; hrow++) {
                    int m = rbase + r*16 + hrow*8;
                    __half2 hh = *(const __half2*)&g_hH[(size_t)m*256 + c];
                    __half2 hl = *(const __half2*)&g_hL[(size_t)m*256 + c];
                    float hv[2];
                    hv[0] = __half2float(__low2half(hh)) + __half2float(__low2half(hl));
                    hv[1] = __half2float(__high2half(hh)) + __half2float(__high2half(hl));
                    float o[2];
#pragma unroll
                    for (int e = 0; e < 2; e++) {
                        int cc = c + e;
                        int fi = hrow*2 + e;
                        float rr = 1.f/(1.f + expf(-(acc[0][r][cgi][fi] +
                                                     b_ih[cc] + b_hh[cc])));
                        float zz = 1.f/(1.f + expf(-(acc[1][r][cgi][fi] +
                                                     b_ih[256+cc] + b_hh[256+cc])));
                        float nn = tanhf(acc[2][r][cgi][fi] + b_ih[512+cc] +
                                         rr*(acc[3][r][cgi][fi] + b_hh[512+cc]));
                        o[e] = nn + zz*(hv[e] - nn);
                    }
                    *(float2*)&g_hn[(size_t)m*256 + c] = make_float2(o[0], o[1]);
                }
            }
        }
    }
}

// ---------------- attention / star update (hn cached in smem) -----------------
#define ATTN_SMEM ((16384 + 256 + 64 + 64 + 64) * 4)

__global__ void __launch_bounds__(256) attn(const float* __restrict__ mask,
                                            float* __restrict__ out,
                                            int final_) {
    extern __shared__ float sm[];
    float* s_hn    = sm;              // 64 x 256
    float* s_star  = sm + 16384;
    float* s_alpha = s_star + 256;
    float* s_v     = s_alpha + 64;
    float* s_p     = s_v + 64;
    int b = blockIdx.x, t = threadIdx.x, lane = t & 31, w = t >> 5;
    s_star[t] = g_star[(size_t)b*256 + t];
    const float4* src = (const float4*)&g_hn[(size_t)b*64*256];
    float4* dst = (float4*)s_hn;
#pragma unroll
    for (int f = 0; f < 16; f++) dst[f*256 + t] = src[f*256 + t];
    __syncthreads();
#pragma unroll
    for (int r = 0; r < 8; r++) {
        int n = w*8 + r;
        float p = 0.f;
#pragma unroll
        for (int j = lane; j < 256; j += 32) p += s_hn[n*256 + j] * s_star[j];
#pragma unroll
        for (int o = 16; o; o >>= 1) p += __shfl_xor_sync(0xffffffffu, p, o);
        if (lane == 0) s_v[n] = p;
    }
    __syncthreads();
    float ss = 0.f;
#pragma unroll 8
    for (int j = 0; j < 256; j++) { float x = s_star[j]; ss += x*x; }
    if (t < 64) {
        float sraw = s_v[t];
        float a = 1.f / (1.f + expf(-sraw * 0.0625f));
        s_alpha[t] = a;
        float d2 = (1.f - a)*sraw + a*ss;
        s_v[t] = expf(d2) * mask[(size_t)b*64 + t];
    }
    __syncthreads();
    float den = 1e-24f;
#pragma unroll
    for (int n = 0; n < 64; n++) den += s_v[n];
    if (t < 64) s_p[t] = s_v[t] / den;
    __syncthreads();
    float st = s_star[t];
    float accS = 0.f;
#pragma unroll 4
    for (int n = 0; n < 64; n++) {
        float a = s_alpha[n];
        size_t idx = ((size_t)b*64 + n)*256 + t;
        float h2 = (1.f - a)*s_hn[n*256 + t] + a*st;
        __half hi, lo; h_split(h2, hi, lo);
        g_hH[idx] = hi; g_hL[idx] = lo;
        if (final_) out[idx] = h2;
        accS += s_p[n] * h2;
    }
    g_star[(size_t)b*256 + t] = accS;
    if (final_) out[(size_t)Bb*Nn*Hh + (size_t)b*256 + t] = accS;
}

// ---------------- launch ------------------------------------------------------
extern "C" void kernel_launch(void* const* d_in, const int* in_sizes, int n_in,
                              void* d_out, int out_size) {
    const float* A      = (const float*)d_in[0];
    const float* hidden = (const float*)d_in[1];
    const float* mask   = (const float*)d_in[2];
    const float* w_ih   = (const float*)d_in[3];
    const float* w_hh   = (const float*)d_in[4];
    const float* b_ih   = (const float*)d_in[5];
    const float* b_hh   = (const float*)d_in[6];
    const float* b_iah  = (const float*)d_in[7];
    const float* b_oah  = (const float*)d_in[8];
    const float* W_in   = (const float*)d_in[9];
    const float* b_in   = (const float*)d_in[10];
    const float* W_out  = (const float*)d_in[11];
    const float* b_out  = (const float*)d_in[12];
    float* out = (float*)d_out;

    cudaFuncSetAttribute(gemm1_mma, cudaFuncAttributeMaxDynamicSharedMemorySize, G1_SMEM);
    cudaFuncSetAttribute(gemm2_mma, cudaFuncAttributeMaxDynamicSharedMemorySize, G2_SMEM);
    cudaFuncSetAttribute(gemm3_mma, cudaFuncAttributeMaxDynamicSharedMemorySize, G3_SMEM);
    cudaFuncSetAttribute(attn,      cudaFuncAttributeMaxDynamicSharedMemorySize, ATTN_SMEM);

    setup_weights<<<1536, 256>>>(W_in, b_in, W_out, b_out, w_ih, w_hh);
    setup_A<<<4096, 256>>>(A);
    init_h<<<Bb, 256>>>(hidden, mask);

    for (int s = 0; s < 2; s++) {
        gemm1_mma<<<dim3(8, 1024), 256, G1_SMEM>>>();
        gemm2_mma<<<dim3(Bb, 2), 256, G2_SMEM>>>(b_iah, b_oah);
        gemm3_mma<<<1024, 256, G3_SMEM>>>(b_ih, b_hh);
        attn<<<Bb, 256, ATTN_SMEM>>>(mask, out, s == 1);
    }
}

// round 11
// speedup vs baseline: 1.2861x; 1.2861x over previous
#include <cuda_runtime.h>
#include <cuda_fp16.h>
#include <math.h>
#include <cstdint>

#define Bb   2048
#define Nn   64
#define Hh   256
#define MTOT (Bb*Nn)          // 131072

// ---------------- scratch (static device globals; no allocations) ----------
__device__ float g_hn  [MTOT*Hh];         // hidden after GRU cell (fp32)
__device__ float g_star[Bb*Hh];
__device__ float g_bias1[512];
// fp16 split activations / rounded weights
__device__ __half g_hH  [MTOT*256];
__device__ __half g_hL  [MTOT*256];       // epilogue-only (exact h reconstruction)
__device__ __half g_hioH[MTOT*512];
__device__ __half g_inpH[MTOT*512];
__device__ __half g_AH  [Bb*64*128];
__device__ __half g_AL  [Bb*64*128];
__device__ __half g_w1  [512*256];        // [c][k]: c<256 W_in, else W_out
__device__ __half g_wih [768*512];        // [n][k]
__device__ __half g_whh [768*256];

// ---------------- helpers ----------------------------------------------------
__device__ __forceinline__ uint32_t smem_u32(const void* p) {
    uint32_t a;
    asm("{ .reg .u64 t; cvta.to.shared.u64 t, %1; cvt.u32.u64 %0, t; }"
        : "=r"(a) : "l"(p));
    return a;
}
__device__ __forceinline__ void cp16(uint32_t dst, const void* src) {
    asm volatile("cp.async.cg.shared.global [%0], [%1], 16;"
                 :: "r"(dst), "l"(src) : "memory");
}
#define CP_COMMIT() asm volatile("cp.async.commit_group;" ::: "memory")
#define CP_WAIT(n)  asm volatile("cp.async.wait_group %0;" :: "n"(n) : "memory")

__device__ __forceinline__ void ldsm_x4(uint32_t& r0, uint32_t& r1,
                                        uint32_t& r2, uint32_t& r3,
                                        uint32_t addr) {
    asm volatile("ldmatrix.sync.aligned.m8n8.x4.shared.b16 {%0,%1,%2,%3}, [%4];"
                 : "=r"(r0), "=r"(r1), "=r"(r2), "=r"(r3) : "r"(addr));
}
__device__ __forceinline__ void ldsm_x4_t(uint32_t& r0, uint32_t& r1,
                                          uint32_t& r2, uint32_t& r3,
                                          uint32_t addr) {
    asm volatile("ldmatrix.sync.aligned.m8n8.x4.trans.shared.b16 {%0,%1,%2,%3}, [%4];"
                 : "=r"(r0), "=r"(r1), "=r"(r2), "=r"(r3) : "r"(addr));
}
__device__ __forceinline__ void mma_f16(float* d,
                                        uint32_t a0, uint32_t a1,
                                        uint32_t a2, uint32_t a3,
                                        uint32_t b0, uint32_t b1) {
    asm volatile(
        "mma.sync.aligned.m16n8k16.row.col.f32.f16.f16.f32 "
        "{%0,%1,%2,%3}, {%4,%5,%6,%7}, {%8,%9}, {%0,%1,%2,%3};"
        : "+f"(d[0]), "+f"(d[1]), "+f"(d[2]), "+f"(d[3])
        : "r"(a0), "r"(a1), "r"(a2), "r"(a3), "r"(b0), "r"(b1));
}
__device__ __forceinline__ void h_split(float v, __half& hi, __half& lo) {
    hi = __float2half_rn(v);
    lo = __float2half_rn(v - __half2float(hi));
}

// ---------------- setup -------------------------------------------------------
__global__ void setup_weights(const float* __restrict__ W_in,
                              const float* __restrict__ b_in,
                              const float* __restrict__ W_out,
                              const float* __restrict__ b_out,
                              const float* __restrict__ w_ih,
                              const float* __restrict__ w_hh) {
    int i = blockIdx.x * blockDim.x + threadIdx.x;
    if (i < 512) g_bias1[i] = (i < 256) ? b_in[i] : b_out[i-256];
    if (i < 512*256) {
        int c = i >> 8, k = i & 255;
        float v = (c < 256) ? W_in[c*256 + k] : W_out[(c-256)*256 + k];
        g_w1[i] = __float2half_rn(v);
    }
    if (i < 768*512) g_wih[i] = __float2half_rn(w_ih[i]);
    if (i < 768*256) g_whh[i] = __float2half_rn(w_hh[i]);
}

__global__ void setup_A(const float* __restrict__ A) {
    size_t n = (size_t)Bb*64*128;
    for (size_t i = blockIdx.x*(size_t)blockDim.x + threadIdx.x; i < n;
         i += (size_t)gridDim.x*blockDim.x) {
        __half hi, lo; h_split(A[i], hi, lo);
        g_AH[i] = hi; g_AL[i] = lo;
    }
}

// fused: split hidden into hH/hL + compute star (masked mean)
__global__ void __launch_bounds__(256) init_h(const float* __restrict__ hidden,
                                              const float* __restrict__ mask) {
    int b = blockIdx.x, t = threadIdx.x;
    float len = 0.f, acc = 0.f;
#pragma unroll 4
    for (int n = 0; n < 64; n++) {
        float mk = mask[b*64 + n];
        size_t idx = ((size_t)b*64 + n)*256 + t;
        float v = hidden[idx];
        __half hi, lo; h_split(v, hi, lo);
        g_hH[idx] = hi; g_hL[idx] = lo;
        acc += v * mk; len += mk;
    }
    g_star[(size_t)b*256 + t] = acc / len;
}

// ---------------- GEMM1 (fp16): hio = h @ [W_in^T|W_out^T] + bias ------------
// CTA 128 rows x 128 cols; warp = 64 rows x 32 cols. 2 CTAs/SM.
#define G1_STAGE 36864   // A 18432 + B 18432
#define G1_SMEM  (2*G1_STAGE)

__device__ __forceinline__ void g1_load(uint32_t sbase, int st, int ch,
                                        int m0, int c0) {
    const int t = threadIdx.x;
    uint32_t sb = sbase + st*G1_STAGE;
    int koff = ch*64;
#pragma unroll
    for (int f = 0; f < 4; f++) {
        int u = f*256 + t; int row = u >> 3, seg = u & 7;
        cp16(sb + row*144 + seg*16,
             g_hH + (size_t)(m0+row)*256 + koff + seg*8);
    }
#pragma unroll
    for (int f = 0; f < 4; f++) {
        int u = f*256 + t; int row = u >> 3, seg = u & 7;
        cp16(sb + 18432 + row*144 + seg*16,
             g_w1 + (size_t)(c0+row)*256 + koff + seg*8);
    }
}

__global__ void __launch_bounds__(256, 2) gemm1_mma() {
    extern __shared__ __align__(16) char smem[];
    const int t = threadIdx.x, wid = t >> 5, lane = t & 31;
    const int c0 = blockIdx.x * 128, m0 = blockIdx.y * 128;
    const int wr = wid >> 2, wc = wid & 3;     // 2 row-groups x 4 col-groups
    uint32_t sbase = smem_u32(smem);
    float acc[4][4][4];                        // [colfrag][rowfrag][4]
#pragma unroll
    for (int cf = 0; cf < 4; cf++)
#pragma unroll
        for (int r = 0; r < 4; r++)
#pragma unroll
            for (int i = 0; i < 4; i++) acc[cf][r][i] = 0.f;

    g1_load(sbase, 0, 0, m0, c0);
    CP_COMMIT();

    const int midx = lane >> 3;
    const int trow = (midx >> 1)*8 + (lane & 7);
    const int kh   = (midx & 1)*16;
    const uint32_t aRow0 = (wr*64 + (lane & 15))*144 + (lane >> 4)*16;

    for (int ch = 0; ch < 4; ch++) {
        if (ch + 1 < 4) {
            g1_load(sbase, (ch + 1) & 1, ch + 1, m0, c0);
            CP_COMMIT();
            CP_WAIT(1);
        } else {
            CP_WAIT(0);
        }
        __syncthreads();
        uint32_t sb = sbase + (ch & 1)*G1_STAGE;
#pragma unroll
        for (int kt = 0; kt < 4; kt++) {
            uint32_t a[4][4];
#pragma unroll
            for (int r = 0; r < 4; r++)
                ldsm_x4(a[r][0], a[r][1], a[r][2], a[r][3],
                        sb + aRow0 + r*16*144 + kt*32);
#pragma unroll
            for (int jj = 0; jj < 2; jj++) {
                uint32_t ba = sb + 18432 + (wc*32 + jj*16 + trow)*144 +
                              kt*32 + kh;
                uint32_t b0, b1, b2, b3;
                ldsm_x4(b0, b1, b2, b3, ba);
#pragma unroll
                for (int r = 0; r < 4; r++) {
                    mma_f16(acc[2*jj][r],   a[r][0], a[r][1], a[r][2], a[r][3], b0, b1);
                    mma_f16(acc[2*jj+1][r], a[r][0], a[r][1], a[r][2], a[r][3], b2, b3);
                }
            }
        }
        __syncthreads();
    }
    const int r0 = m0 + wr*64 + (lane >> 2);
    const int cb = (lane & 3)*2;
#pragma unroll
    for (int cf = 0; cf < 4; cf++) {
        int c = c0 + wc*32 + cf*8 + cb;
        float2 bz = *(const float2*)&g_bias1[c];
#pragma unroll
        for (int r = 0; r < 4; r++) {
#pragma unroll
            for (int hrow = 0; hrow < 2; hrow++) {
                int m = r0 + r*16 + hrow*8;
                float v0 = acc[cf][r][hrow*2]   + bz.x;
                float v1 = acc[cf][r][hrow*2+1] + bz.y;
                *(__half2*)&g_hioH[(size_t)m*512 + c] =
                    __halves2half2(__float2half_rn(v0), __float2half_rn(v1));
            }
        }
    }
}

// ---------------- GEMM2 (fp16x2): inp = A_adj @ hio + bias --------------------
#define G2_A   0          // 2 planes x 64 x 144 = 18432
#define G2_B   18432      // 1 plane  x 64 x 528 = 33792
#define G2_SMEM 52224

__global__ void __launch_bounds__(256, 2) gemm2_mma(const float* __restrict__ b_iah,
                                                    const float* __restrict__ b_oah) {
    extern __shared__ __align__(16) char smem[];
    const int t = threadIdx.x, wid = t >> 5, lane = t & 31;
    const int b = blockIdx.x, half_ = blockIdx.y;
    uint32_t sbase = smem_u32(smem);
#pragma unroll
    for (int f = 0; f < 4; f++) {
        int u = f*256 + t; int pl = u >> 9, row = (u >> 3) & 63, seg = u & 7;
        const __half* src = pl ? g_AL : g_AH;
        cp16(sbase + G2_A + pl*9216 + row*144 + seg*16,
             src + (size_t)b*8192 + row*128 + half_*64 + seg*8);
    }
#pragma unroll
    for (int f = 0; f < 8; f++) {
        int u = f*256 + t; int row = u >> 5, seg = u & 31;
        cp16(sbase + G2_B + row*528 + seg*16,
             g_hioH + ((size_t)b*64 + row)*512 + half_*256 + seg*8);
    }
    CP_COMMIT(); CP_WAIT(0);
    __syncthreads();

    const int wr = wid >> 2, wc = wid & 3;
    float acc[2][8][4];
#pragma unroll
    for (int r = 0; r < 2; r++)
#pragma unroll
        for (int j = 0; j < 8; j++)
#pragma unroll
            for (int i = 0; i < 4; i++) acc[r][j][i] = 0.f;

    uint32_t aBase = sbase + G2_A + (wr*32 + (lane & 15))*144 + (lane >> 4)*16;
#pragma unroll
    for (int kt = 0; kt < 4; kt++) {
        uint32_t ah[2][4], al[2][4];
#pragma unroll
        for (int r = 0; r < 2; r++) {
            ldsm_x4(ah[r][0], ah[r][1], ah[r][2], ah[r][3],
                    aBase + r*2304 + kt*32);
            ldsm_x4(al[r][0], al[r][1], al[r][2], al[r][3],
                    aBase + 9216 + r*2304 + kt*32);
        }
#pragma unroll
        for (int jj = 0; jj < 4; jj++) {
            uint32_t ba = sbase + G2_B + (kt*16 + (lane & 15))*528 +
                          (wc*64 + jj*16 + (lane >> 4)*8)*2;
            uint32_t bh0, bh1, bh2, bh3;
            ldsm_x4_t(bh0, bh1, bh2, bh3, ba);
#pragma unroll
            for (int r = 0; r < 2; r++) {
                mma_f16(acc[r][jj*2],   ah[r][0], ah[r][1], ah[r][2], ah[r][3], bh0, bh1);
                mma_f16(acc[r][jj*2+1], ah[r][0], ah[r][1], ah[r][2], ah[r][3], bh2, bh3);
                mma_f16(acc[r][jj*2],   al[r][0], al[r][1], al[r][2], al[r][3], bh0, bh1);
                mma_f16(acc[r][jj*2+1], al[r][0], al[r][1], al[r][2], al[r][3], bh2, bh3);
            }
        }
    }
    const float* bias = half_ ? b_oah : b_iah;
#pragma unroll
    for (int r = 0; r < 2; r++) {
        int n = wr*32 + r*16 + (lane >> 2);
#pragma unroll
        for (int j = 0; j < 8; j++) {
            int col = wc*64 + j*8 + (lane & 3)*2;
#pragma unroll
            for (int hrow = 0; hrow < 2; hrow++) {
                int nn = n + hrow*8;
                float v0 = acc[r][j][hrow*2]   + bias[col];
                float v1 = acc[r][j][hrow*2+1] + bias[col+1];
                size_t o = ((size_t)b*64 + nn)*512 + half_*256 + col;
                *(__half2*)&g_inpH[o] =
                    __halves2half2(__float2half_rn(v0), __float2half_rn(v1));
            }
        }
    }
}

// ---------------- GEMM3: gates + fused GRU (R9 version) ------------------------
#define G3_B     18432    // A hi
#define G3_STAGE 32256    // + B 96 x 144 = 13824
#define G3_BIAS  (2*G3_STAGE)
#define G3_SMEM  (G3_BIAS + 768)

__device__ __forceinline__ void g3_load(uint32_t sbase, int st, int ch,
                                        int m0, int c0) {
    const int t = threadIdx.x;
    uint32_t sb = sbase + st*G3_STAGE;
    const __half *Ah, *Bw; int ak, koff;
    if (ch < 8) { Ah = g_inpH; Bw = g_wih; ak = 512; koff = ch*64; }
    else        { Ah = g_hH;   Bw = g_whh; ak = 256; koff = (ch-8)*64; }
#pragma unroll
    for (int f = 0; f < 4; f++) {
        int u = f*256 + t; int row = u >> 3, seg = u & 7;
        cp16(sb + row*144 + seg*16,
             Ah + (size_t)(m0+row)*ak + koff + seg*8);
    }
#pragma unroll
    for (int f = 0; f < 3; f++) {
        int u = f*256 + t; int row = u >> 3, seg = u & 7;
        int g = row >> 5, n = row & 31;
        cp16(sb + G3_B + row*144 + seg*16,
             Bw + (size_t)(g*256 + c0 + n)*ak + koff + seg*8);
    }
}

template<bool GH>
__device__ __forceinline__ void g3_mma_chunk(uint32_t sb, int wr, int wc, int lane,
                                             float (&acc)[4][2][2][4]) {
    uint32_t aBase = sb + (wr*32 + (lane & 15))*144 + (lane >> 4)*16;
    const int midx = lane >> 3;
    const int trow = (midx >> 1)*8 + (lane & 7);
    const int kh   = (midx & 1)*16;
#pragma unroll
    for (int kt = 0; kt < 4; kt++) {
        uint32_t a[2][4];
#pragma unroll
        for (int r = 0; r < 2; r++)
            ldsm_x4(a[r][0], a[r][1], a[r][2], a[r][3],
                    aBase + r*2304 + kt*32);
#pragma unroll
        for (int g = 0; g < 3; g++) {
            const int p = (!GH || g < 2) ? g : 3;
            uint32_t b0, b1, b2, b3;
            ldsm_x4(b0, b1, b2, b3,
                    sb + G3_B + (g*32 + wc*16 + trow)*144 + kt*32 + kh);
#pragma unroll
            for (int r = 0; r < 2; r++) {
                mma_f16(acc[p][r][0], a[r][0], a[r][1], a[r][2], a[r][3], b0, b1);
                mma_f16(acc[p][r][1], a[r][0], a[r][1], a[r][2], a[r][3], b2, b3);
            }
        }
    }
}

__global__ void __launch_bounds__(256, 2) gemm3_mma(const float* __restrict__ b_ih,
                                                    const float* __restrict__ b_hh) {
    extern __shared__ __align__(16) char smem[];
    const int t = threadIdx.x, wid = t >> 5, lane = t & 31;
    const int c0 = blockIdx.x * 32, m0 = blockIdx.y * 128;
    const int wr = wid & 3, wc = wid >> 2;
    uint32_t sbase = smem_u32(smem);
    float* sbih = (float*)(smem + G3_BIAS);
    float* sbhh = (float*)(smem + G3_BIAS + 384);
    if (t < 32) {
#pragma unroll
        for (int g = 0; g < 3; g++) {
            sbih[g*32 + t] = b_ih[g*256 + c0 + t];
            sbhh[g*32 + t] = b_hh[g*256 + c0 + t];
        }
    }
    float acc[4][2][2][4];
#pragma unroll
    for (int p = 0; p < 4; p++)
#pragma unroll
        for (int r = 0; r < 2; r++)
#pragma unroll
            for (int cgi = 0; cgi < 2; cgi++)
#pragma unroll
                for (int i = 0; i < 4; i++) acc[p][r][cgi][i] = 0.f;

    g3_load(sbase, 0, 0, m0, c0);
    CP_COMMIT();

    for (int ch = 0; ch < 12; ch++) {
        if (ch + 1 < 12) {
            g3_load(sbase, (ch + 1) & 1, ch + 1, m0, c0);
            CP_COMMIT();
            CP_WAIT(1);
        } else {
            CP_WAIT(0);
        }
        __syncthreads();
        uint32_t sb = sbase + (ch & 1)*G3_STAGE;
        if (ch < 8) g3_mma_chunk<false>(sb, wr, wc, lane, acc);
        else        g3_mma_chunk<true >(sb, wr, wc, lane, acc);
        __syncthreads();
    }

    // GRU epilogue (h reconstructed exactly from fp16 hi/lo pair)
    const int rbase = m0 + wr*32 + (lane >> 2);
    const int cb = (lane & 3)*2;
#pragma unroll
    for (int r = 0; r < 2; r++) {
#pragma unroll
        for (int cgi = 0; cgi < 2; cgi++) {
            int cl = wc*16 + cgi*8 + cb;
            int c  = c0 + cl;
#pragma unroll
            for (int hrow = 0; hrow < 2; hrow++) {
                int m = rbase + r*16 + hrow*8;
                __half2 hh = *(const __half2*)&g_hH[(size_t)m*256 + c];
                __half2 hl = *(const __half2*)&g_hL[(size_t)m*256 + c];
                float hv[2];
                hv[0] = __half2float(__low2half(hh)) + __half2float(__low2half(hl));
                hv[1] = __half2float(__high2half(hh)) + __half2float(__high2half(hl));
                float o[2];
#pragma unroll
                for (int e = 0; e < 2; e++) {
                    int li = cl + e;
                    int fi = hrow*2 + e;
                    float rr = 1.f/(1.f + expf(-(acc[0][r][cgi][fi] +
                                                 sbih[li] + sbhh[li])));
                    float zz = 1.f/(1.f + expf(-(acc[1][r][cgi][fi] +
                                                 sbih[32+li] + sbhh[32+li])));
                    float nn = tanhf(acc[2][r][cgi][fi] + sbih[64+li] +
                                     rr*(acc[3][r][cgi][fi] + sbhh[64+li]));
                    o[e] = nn + zz*(hv[e] - nn);
                }
                *(float2*)&g_hn[(size_t)m*256 + c] = make_float2(o[0], o[1]);
            }
        }
    }
}

// ---------------- attention / star update (hn cached in smem) -----------------
#define ATTN_SMEM ((16384 + 256 + 64 + 64 + 64) * 4)

__global__ void __launch_bounds__(256) attn(const float* __restrict__ mask,
                                            float* __restrict__ out,
                                            int final_) {
    extern __shared__ float sm[];
    float* s_hn    = sm;              // 64 x 256
    float* s_star  = sm + 16384;
    float* s_alpha = s_star + 256;
    float* s_v     = s_alpha + 64;
    float* s_p     = s_v + 64;
    int b = blockIdx.x, t = threadIdx.x, lane = t & 31, w = t >> 5;
    s_star[t] = g_star[(size_t)b*256 + t];
    const float4* src = (const float4*)&g_hn[(size_t)b*64*256];
    float4* dst = (float4*)s_hn;
#pragma unroll
    for (int f = 0; f < 16; f++) dst[f*256 + t] = src[f*256 + t];
    __syncthreads();
#pragma unroll
    for (int r = 0; r < 8; r++) {
        int n = w*8 + r;
        float p = 0.f;
#pragma unroll
        for (int j = lane; j < 256; j += 32) p += s_hn[n*256 + j] * s_star[j];
#pragma unroll
        for (int o = 16; o; o >>= 1) p += __shfl_xor_sync(0xffffffffu, p, o);
        if (lane == 0) s_v[n] = p;
    }
    __syncthreads();
    float ss = 0.f;
#pragma unroll 8
    for (int j = 0; j < 256; j++) { float x = s_star[j]; ss += x*x; }
    if (t < 64) {
        float sraw = s_v[t];
        float a = 1.f / (1.f + expf(-sraw * 0.0625f));
        s_alpha[t] = a;
        float d2 = (1.f - a)*sraw + a*ss;
        s_v[t] = expf(d2) * mask[(size_t)b*64 + t];
    }
    __syncthreads();
    float den = 1e-24f;
#pragma unroll
    for (int n = 0; n < 64; n++) den += s_v[n];
    if (t < 64) s_p[t] = s_v[t] / den;
    __syncthreads();
    float st = s_star[t];
    float accS = 0.f;
#pragma unroll 4
    for (int n = 0; n < 64; n++) {
        float a = s_alpha[n];
        size_t idx = ((size_t)b*64 + n)*256 + t;
        float h2 = (1.f - a)*s_hn[n*256 + t] + a*st;
        __half hi, lo; h_split(h2, hi, lo);
        g_hH[idx] = hi; g_hL[idx] = lo;
        if (final_) out[idx] = h2;
        accS += s_p[n] * h2;
    }
    g_star[(size_t)b*256 + t] = accS;
    if (final_) out[(size_t)Bb*Nn*Hh + (size_t)b*256 + t] = accS;
}

// ---------------- launch ------------------------------------------------------
extern "C" void kernel_launch(void* const* d_in, const int* in_sizes, int n_in,
                              void* d_out, int out_size) {
    const float* A      = (const float*)d_in[0];
    const float* hidden = (const float*)d_in[1];
    const float* mask   = (const float*)d_in[2];
    const float* w_ih   = (const float*)d_in[3];
    const float* w_hh   = (const float*)d_in[4];
    const float* b_ih   = (const float*)d_in[5];
    const float* b_hh   = (const float*)d_in[6];
    const float* b_iah  = (const float*)d_in[7];
    const float* b_oah  = (const float*)d_in[8];
    const float* W_in   = (const float*)d_in[9];
    const float* b_in   = (const float*)d_in[10];
    const float* W_out  = (const float*)d_in[11];
    const float* b_out  = (const float*)d_in[12];
    float* out = (float*)d_out;

    cudaFuncSetAttribute(gemm1_mma, cudaFuncAttributeMaxDynamicSharedMemorySize, G1_SMEM);
    cudaFuncSetAttribute(gemm2_mma, cudaFuncAttributeMaxDynamicSharedMemorySize, G2_SMEM);
    cudaFuncSetAttribute(gemm3_mma, cudaFuncAttributeMaxDynamicSharedMemorySize, G3_SMEM);
    cudaFuncSetAttribute(attn,      cudaFuncAttributeMaxDynamicSharedMemorySize, ATTN_SMEM);

    setup_weights<<<1536, 256>>>(W_in, b_in, W_out, b_out, w_ih, w_hh);
    setup_A<<<4096, 256>>>(A);
    init_h<<<Bb, 256>>>(hidden, mask);

    for (int s = 0; s < 2; s++) {
        gemm1_mma<<<dim3(4, 1024), 256, G1_SMEM>>>();
        gemm2_mma<<<dim3(Bb, 2), 256, G2_SMEM>>>(b_iah, b_oah);
        gemm3_mma<<<dim3(8, 1024), 256, G3_SMEM>>>(b_ih, b_hh);
        attn<<<Bb, 256, ATTN_SMEM>>>(mask, out, s == 1);
    }
}

// round 12
// speedup vs baseline: 1.3222x; 1.0281x over previous
#include <cuda_runtime.h>
#include <cuda_fp16.h>
#include <math.h>
#include <cstdint>

#define Bb   2048
#define Nn   64
#define Hh   256
#define MTOT (Bb*Nn)          // 131072

// ---------------- scratch (static device globals; no allocations) ----------
__device__ float g_hn  [MTOT*Hh];
__device__ float g_star[Bb*Hh];
__device__ float g_bias1[512];
__device__ __half g_hH  [MTOT*256];
__device__ __half g_hL  [MTOT*256];       // epilogue-only
__device__ __half g_inpH[MTOT*512];
__device__ __half g_AH  [Bb*64*128];
__device__ __half g_AL  [Bb*64*128];
__device__ __half g_w1  [512*256];        // [c][k]
__device__ __half g_wih [768*512];
__device__ __half g_whh [768*256];

// ---------------- helpers ----------------------------------------------------
__device__ __forceinline__ uint32_t smem_u32(const void* p) {
    uint32_t a;
    asm("{ .reg .u64 t; cvta.to.shared.u64 t, %1; cvt.u32.u64 %0, t; }"
        : "=r"(a) : "l"(p));
    return a;
}
__device__ __forceinline__ void cp16(uint32_t dst, const void* src) {
    asm volatile("cp.async.cg.shared.global [%0], [%1], 16;"
                 :: "r"(dst), "l"(src) : "memory");
}
#define CP_COMMIT() asm volatile("cp.async.commit_group;" ::: "memory")
#define CP_WAIT(n)  asm volatile("cp.async.wait_group %0;" :: "n"(n) : "memory")

__device__ __forceinline__ void ldsm_x4(uint32_t& r0, uint32_t& r1,
                                        uint32_t& r2, uint32_t& r3,
                                        uint32_t addr) {
    asm volatile("ldmatrix.sync.aligned.m8n8.x4.shared.b16 {%0,%1,%2,%3}, [%4];"
                 : "=r"(r0), "=r"(r1), "=r"(r2), "=r"(r3) : "r"(addr));
}
__device__ __forceinline__ void ldsm_x4_t(uint32_t& r0, uint32_t& r1,
                                          uint32_t& r2, uint32_t& r3,
                                          uint32_t addr) {
    asm volatile("ldmatrix.sync.aligned.m8n8.x4.trans.shared.b16 {%0,%1,%2,%3}, [%4];"
                 : "=r"(r0), "=r"(r1), "=r"(r2), "=r"(r3) : "r"(addr));
}
__device__ __forceinline__ void mma_f16(float* d,
                                        uint32_t a0, uint32_t a1,
                                        uint32_t a2, uint32_t a3,
                                        uint32_t b0, uint32_t b1) {
    asm volatile(
        "mma.sync.aligned.m16n8k16.row.col.f32.f16.f16.f32 "
        "{%0,%1,%2,%3}, {%4,%5,%6,%7}, {%8,%9}, {%0,%1,%2,%3};"
        : "+f"(d[0]), "+f"(d[1]), "+f"(d[2]), "+f"(d[3])
        : "r"(a0), "r"(a1), "r"(a2), "r"(a3), "r"(b0), "r"(b1));
}
__device__ __forceinline__ void h_split(float v, __half& hi, __half& lo) {
    hi = __float2half_rn(v);
    lo = __float2half_rn(v - __half2float(hi));
}

// ---------------- setup -------------------------------------------------------
__global__ void setup_weights(const float* __restrict__ W_in,
                              const float* __restrict__ b_in,
                              const float* __restrict__ W_out,
                              const float* __restrict__ b_out,
                              const float* __restrict__ w_ih,
                              const float* __restrict__ w_hh) {
    int i = blockIdx.x * blockDim.x + threadIdx.x;
    if (i < 512) g_bias1[i] = (i < 256) ? b_in[i] : b_out[i-256];
    if (i < 512*256) {
        int c = i >> 8, k = i & 255;
        float v = (c < 256) ? W_in[c*256 + k] : W_out[(c-256)*256 + k];
        g_w1[i] = __float2half_rn(v);
    }
    if (i < 768*512) g_wih[i] = __float2half_rn(w_ih[i]);
    if (i < 768*256) g_whh[i] = __float2half_rn(w_hh[i]);
}

__global__ void setup_A(const float* __restrict__ A) {
    size_t n = (size_t)Bb*64*128;
    for (size_t i = blockIdx.x*(size_t)blockDim.x + threadIdx.x; i < n;
         i += (size_t)gridDim.x*blockDim.x) {
        __half hi, lo; h_split(A[i], hi, lo);
        g_AH[i] = hi; g_AL[i] = lo;
    }
}

__global__ void __launch_bounds__(256) init_h(const float* __restrict__ hidden,
                                              const float* __restrict__ mask) {
    int b = blockIdx.x, t = threadIdx.x;
    float len = 0.f, acc = 0.f;
#pragma unroll 4
    for (int n = 0; n < 64; n++) {
        float mk = mask[b*64 + n];
        size_t idx = ((size_t)b*64 + n)*256 + t;
        float v = hidden[idx];
        __half hi, lo; h_split(v, hi, lo);
        g_hH[idx] = hi; g_hL[idx] = lo;
        acc += v * mk; len += mk;
    }
    g_star[(size_t)b*256 + t] = acc / len;
}

// ---------------- FUSED GEMM1+GEMM2 -------------------------------------------
// CTA per (b, half). Phase 1: hio_half = h[b] @ w1_half^T + bias (smem-resident).
// Phase 2: inp_half = A_half @ hio_half + bias (fp16x2 adjacency split).
// smem: h 64x528=33792 | w1 2x(256x80)=40960 (hio 64x528 overlays) | A 2x9216
#define F_H    0
#define F_W    33792
#define F_A    74752
#define F_SMEM 93184

__device__ __forceinline__ void f_load_w1(uint32_t sbase, int st, int ch, int half_) {
    const int t = threadIdx.x;
    uint32_t sb = sbase + F_W + st*20480;
#pragma unroll
    for (int f = 0; f < 4; f++) {
        int u = f*256 + t; int row = u >> 2, seg = u & 3;
        cp16(sb + row*80 + seg*16,
             g_w1 + (size_t)(half_*256 + row)*256 + ch*32 + seg*8);
    }
}

__global__ void __launch_bounds__(256, 2) gemm12_mma(const float* __restrict__ b_iah,
                                                     const float* __restrict__ b_oah) {
    extern __shared__ __align__(16) char smem[];
    const int t = threadIdx.x, wid = t >> 5, lane = t & 31;
    const int b = blockIdx.x, half_ = blockIdx.y;
    const int wr = wid >> 2, wc = wid & 3;      // 2 row x 4 col groups
    uint32_t sbase = smem_u32(smem);

    // group 0: h tile + adjacency tiles
#pragma unroll
    for (int f = 0; f < 8; f++) {
        int u = f*256 + t; int row = u >> 5, seg = u & 31;
        cp16(sbase + F_H + row*528 + seg*16,
             g_hH + ((size_t)b*64 + row)*256 + seg*8);
    }
#pragma unroll
    for (int f = 0; f < 4; f++) {
        int u = f*256 + t; int pl = u >> 9, row = (u >> 3) & 63, seg = u & 7;
        const __half* src = pl ? g_AL : g_AH;
        cp16(sbase + F_A + pl*9216 + row*144 + seg*16,
             src + (size_t)b*8192 + row*128 + half_*64 + seg*8);
    }
    CP_COMMIT();
    f_load_w1(sbase, 0, 0, half_);
    CP_COMMIT();

    const int midx = lane >> 3;
    const int trow = (midx >> 1)*8 + (lane & 7);
    const int kh   = (midx & 1)*16;

    // ---- phase 1: hio = h @ w1_half^T  (out 64x256, K=256 in 8 chunks of 32)
    {
        float acc[8][2][4];
#pragma unroll
        for (int cf = 0; cf < 8; cf++)
#pragma unroll
            for (int r = 0; r < 2; r++)
#pragma unroll
                for (int i = 0; i < 4; i++) acc[cf][r][i] = 0.f;

        const uint32_t aRow0 = sbase + F_H + (wr*32 + (lane & 15))*528 +
                               (lane >> 4)*16;
        for (int ch = 0; ch < 8; ch++) {
            if (ch + 1 < 8) {
                f_load_w1(sbase, (ch + 1) & 1, ch + 1, half_);
                CP_COMMIT();
                CP_WAIT(1);
            } else {
                CP_WAIT(0);
            }
            __syncthreads();
            uint32_t sbW = sbase + F_W + (ch & 1)*20480;
#pragma unroll
            for (int kt = 0; kt < 2; kt++) {
                uint32_t a[2][4];
#pragma unroll
                for (int r = 0; r < 2; r++)
                    ldsm_x4(a[r][0], a[r][1], a[r][2], a[r][3],
                            aRow0 + r*16*528 + ch*64 + kt*32);
#pragma unroll
                for (int cf4 = 0; cf4 < 4; cf4++) {
                    uint32_t ba = sbW + (wc*64 + cf4*16 + trow)*80 + kt*32 + kh;
                    uint32_t b0, b1, b2, b3;
                    ldsm_x4(b0, b1, b2, b3, ba);
#pragma unroll
                    for (int r = 0; r < 2; r++) {
                        mma_f16(acc[cf4*2][r],   a[r][0], a[r][1], a[r][2], a[r][3], b0, b1);
                        mma_f16(acc[cf4*2+1][r], a[r][0], a[r][1], a[r][2], a[r][3], b2, b3);
                    }
                }
            }
            __syncthreads();
        }
        // epilogue -> hio tile in smem (overlays w1 stages)
        const int r0 = wr*32 + (lane >> 2);
        const int cb = (lane & 3)*2;
#pragma unroll
        for (int cf = 0; cf < 8; cf++) {
            int c  = wc*64 + cf*8 + cb;          // 0..255 local
            float2 bz = *(const float2*)&g_bias1[half_*256 + c];
#pragma unroll
            for (int r = 0; r < 2; r++) {
#pragma unroll
                for (int hrow = 0; hrow < 2; hrow++) {
                    int row = r0 + r*16 + hrow*8;
                    float v0 = acc[cf][r][hrow*2]   + bz.x;
                    float v1 = acc[cf][r][hrow*2+1] + bz.y;
                    *(__half2*)(smem + F_W + row*528 + c*2) =
                        __halves2half2(__float2half_rn(v0), __float2half_rn(v1));
                }
            }
        }
    }
    __syncthreads();

    // ---- phase 2: inp = A_adj @ hio + bias (fp16x2) ----
    {
        float acc[2][8][4];
#pragma unroll
        for (int r = 0; r < 2; r++)
#pragma unroll
            for (int j = 0; j < 8; j++)
#pragma unroll
                for (int i = 0; i < 4; i++) acc[r][j][i] = 0.f;

        uint32_t aBase = sbase + F_A + (wr*32 + (lane & 15))*144 + (lane >> 4)*16;
#pragma unroll
        for (int kt = 0; kt < 4; kt++) {
            uint32_t ah[2][4], al[2][4];
#pragma unroll
            for (int r = 0; r < 2; r++) {
                ldsm_x4(ah[r][0], ah[r][1], ah[r][2], ah[r][3],
                        aBase + r*2304 + kt*32);
                ldsm_x4(al[r][0], al[r][1], al[r][2], al[r][3],
                        aBase + 9216 + r*2304 + kt*32);
            }
#pragma unroll
            for (int jj = 0; jj < 4; jj++) {
                uint32_t ba = sbase + F_W + (kt*16 + (lane & 15))*528 +
                              (wc*64 + jj*16 + (lane >> 4)*8)*2;
                uint32_t bh0, bh1, bh2, bh3;
                ldsm_x4_t(bh0, bh1, bh2, bh3, ba);
#pragma unroll
                for (int r = 0; r < 2; r++) {
                    mma_f16(acc[r][jj*2],   ah[r][0], ah[r][1], ah[r][2], ah[r][3], bh0, bh1);
                    mma_f16(acc[r][jj*2+1], ah[r][0], ah[r][1], ah[r][2], ah[r][3], bh2, bh3);
                    mma_f16(acc[r][jj*2],   al[r][0], al[r][1], al[r][2], al[r][3], bh0, bh1);
                    mma_f16(acc[r][jj*2+1], al[r][0], al[r][1], al[r][2], al[r][3], bh2, bh3);
                }
            }
        }
        const float* bias = half_ ? b_oah : b_iah;
#pragma unroll
        for (int r = 0; r < 2; r++) {
            int n = wr*32 + r*16 + (lane >> 2);
#pragma unroll
            for (int j = 0; j < 8; j++) {
                int col = wc*64 + j*8 + (lane & 3)*2;
#pragma unroll
                for (int hrow = 0; hrow < 2; hrow++) {
                    int nn = n + hrow*8;
                    float v0 = acc[r][j][hrow*2]   + bias[col];
                    float v1 = acc[r][j][hrow*2+1] + bias[col+1];
                    size_t o = ((size_t)b*64 + nn)*512 + half_*256 + col;
                    *(__half2*)&g_inpH[o] =
                        __halves2half2(__float2half_rn(v0), __float2half_rn(v1));
                }
            }
        }
    }
}

// ---------------- GEMM3: gates + fused GRU ------------------------------------
#define G3_B     18432
#define G3_STAGE 32256
#define G3_BIAS  (2*G3_STAGE)
#define G3_SMEM  (G3_BIAS + 768)

__device__ __forceinline__ void g3_load(uint32_t sbase, int st, int ch,
                                        int m0, int c0) {
    const int t = threadIdx.x;
    uint32_t sb = sbase + st*G3_STAGE;
    const __half *Ah, *Bw; int ak, koff;
    if (ch < 8) { Ah = g_inpH; Bw = g_wih; ak = 512; koff = ch*64; }
    else        { Ah = g_hH;   Bw = g_whh; ak = 256; koff = (ch-8)*64; }
#pragma unroll
    for (int f = 0; f < 4; f++) {
        int u = f*256 + t; int row = u >> 3, seg = u & 7;
        cp16(sb + row*144 + seg*16,
             Ah + (size_t)(m0+row)*ak + koff + seg*8);
    }
#pragma unroll
    for (int f = 0; f < 3; f++) {
        int u = f*256 + t; int row = u >> 3, seg = u & 7;
        int g = row >> 5, n = row & 31;
        cp16(sb + G3_B + row*144 + seg*16,
             Bw + (size_t)(g*256 + c0 + n)*ak + koff + seg*8);
    }
}

template<bool GH>
__device__ __forceinline__ void g3_mma_chunk(uint32_t sb, int wr, int wc, int lane,
                                             float (&acc)[4][2][2][4]) {
    uint32_t aBase = sb + (wr*32 + (lane & 15))*144 + (lane >> 4)*16;
    const int midx = lane >> 3;
    const int trow = (midx >> 1)*8 + (lane & 7);
    const int kh   = (midx & 1)*16;
#pragma unroll
    for (int kt = 0; kt < 4; kt++) {
        uint32_t a[2][4];
#pragma unroll
        for (int r = 0; r < 2; r++)
            ldsm_x4(a[r][0], a[r][1], a[r][2], a[r][3],
                    aBase + r*2304 + kt*32);
#pragma unroll
        for (int g = 0; g < 3; g++) {
            const int p = (!GH || g < 2) ? g : 3;
            uint32_t b0, b1, b2, b3;
            ldsm_x4(b0, b1, b2, b3,
                    sb + G3_B + (g*32 + wc*16 + trow)*144 + kt*32 + kh);
#pragma unroll
            for (int r = 0; r < 2; r++) {
                mma_f16(acc[p][r][0], a[r][0], a[r][1], a[r][2], a[r][3], b0, b1);
                mma_f16(acc[p][r][1], a[r][0], a[r][1], a[r][2], a[r][3], b2, b3);
            }
        }
    }
}

__global__ void __launch_bounds__(256, 2) gemm3_mma(const float* __restrict__ b_ih,
                                                    const float* __restrict__ b_hh) {
    extern __shared__ __align__(16) char smem[];
    const int t = threadIdx.x, wid = t >> 5, lane = t & 31;
    const int c0 = blockIdx.x * 32, m0 = blockIdx.y * 128;
    const int wr = wid & 3, wc = wid >> 2;
    uint32_t sbase = smem_u32(smem);
    float* sbih = (float*)(smem + G3_BIAS);
    float* sbhh = (float*)(smem + G3_BIAS + 384);
    if (t < 32) {
#pragma unroll
        for (int g = 0; g < 3; g++) {
            sbih[g*32 + t] = b_ih[g*256 + c0 + t];
            sbhh[g*32 + t] = b_hh[g*256 + c0 + t];
        }
    }
    float acc[4][2][2][4];
#pragma unroll
    for (int p = 0; p < 4; p++)
#pragma unroll
        for (int r = 0; r < 2; r++)
#pragma unroll
            for (int cgi = 0; cgi < 2; cgi++)
#pragma unroll
                for (int i = 0; i < 4; i++) acc[p][r][cgi][i] = 0.f;

    g3_load(sbase, 0, 0, m0, c0);
    CP_COMMIT();

    for (int ch = 0; ch < 12; ch++) {
        if (ch + 1 < 12) {
            g3_load(sbase, (ch + 1) & 1, ch + 1, m0, c0);
            CP_COMMIT();
            CP_WAIT(1);
        } else {
            CP_WAIT(0);
        }
        __syncthreads();
        uint32_t sb = sbase + (ch & 1)*G3_STAGE;
        if (ch < 8) g3_mma_chunk<false>(sb, wr, wc, lane, acc);
        else        g3_mma_chunk<true >(sb, wr, wc, lane, acc);
        __syncthreads();
    }

    const int rbase = m0 + wr*32 + (lane >> 2);
    const int cb = (lane & 3)*2;
#pragma unroll
    for (int r = 0; r < 2; r++) {
#pragma unroll
        for (int cgi = 0; cgi < 2; cgi++) {
            int cl = wc*16 + cgi*8 + cb;
            int c  = c0 + cl;
#pragma unroll
            for (int hrow = 0; hrow < 2; hrow++) {
                int m = rbase + r*16 + hrow*8;
                __half2 hh = *(const __half2*)&g_hH[(size_t)m*256 + c];
                __half2 hl = *(const __half2*)&g_hL[(size_t)m*256 + c];
                float hv[2];
                hv[0] = __half2float(__low2half(hh)) + __half2float(__low2half(hl));
                hv[1] = __half2float(__high2half(hh)) + __half2float(__high2half(hl));
                float o[2];
#pragma unroll
                for (int e = 0; e < 2; e++) {
                    int li = cl + e;
                    int fi = hrow*2 + e;
                    float rr = 1.f/(1.f + expf(-(acc[0][r][cgi][fi] +
                                                 sbih[li] + sbhh[li])));
                    float zz = 1.f/(1.f + expf(-(acc[1][r][cgi][fi] +
                                                 sbih[32+li] + sbhh[32+li])));
                    float nn = tanhf(acc[2][r][cgi][fi] + sbih[64+li] +
                                     rr*(acc[3][r][cgi][fi] + sbhh[64+li]));
                    o[e] = nn + zz*(hv[e] - nn);
                }
                *(float2*)&g_hn[(size_t)m*256 + c] = make_float2(o[0], o[1]);
            }
        }
    }
}

// ---------------- attention / star update -------------------------------------
#define ATTN_SMEM ((16384 + 256 + 64 + 64 + 64) * 4)

__global__ void __launch_bounds__(256) attn(const float* __restrict__ mask,
                                            float* __restrict__ out,
                                            int final_) {
    extern __shared__ float sm[];
    float* s_hn    = sm;
    float* s_star  = sm + 16384;
    float* s_alpha = s_star + 256;
    float* s_v     = s_alpha + 64;
    float* s_p     = s_v + 64;
    int b = blockIdx.x, t = threadIdx.x, lane = t & 31, w = t >> 5;
    s_star[t] = g_star[(size_t)b*256 + t];
    const float4* src = (const float4*)&g_hn[(size_t)b*64*256];
    float4* dst = (float4*)s_hn;
#pragma unroll
    for (int f = 0; f < 16; f++) dst[f*256 + t] = src[f*256 + t];
    __syncthreads();
#pragma unroll
    for (int r = 0; r < 8; r++) {
        int n = w*8 + r;
        float p = 0.f;
#pragma unroll
        for (int j = lane; j < 256; j += 32) p += s_hn[n*256 + j] * s_star[j];
#pragma unroll
        for (int o = 16; o; o >>= 1) p += __shfl_xor_sync(0xffffffffu, p, o);
        if (lane == 0) s_v[n] = p;
    }
    __syncthreads();
    float ss = 0.f;
#pragma unroll 8
    for (int j = 0; j < 256; j++) { float x = s_star[j]; ss += x*x; }
    if (t < 64) {
        float sraw = s_v[t];
        float a = 1.f / (1.f + expf(-sraw * 0.0625f));
        s_alpha[t] = a;
        float d2 = (1.f - a)*sraw + a*ss;
        s_v[t] = expf(d2) * mask[(size_t)b*64 + t];
    }
    __syncthreads();
    float den = 1e-24f;
#pragma unroll
    for (int n = 0; n < 64; n++) den += s_v[n];
    if (t < 64) s_p[t] = s_v[t] / den;
    __syncthreads();
    float st = s_star[t];
    float accS = 0.f;
#pragma unroll 4
    for (int n = 0; n < 64; n++) {
        float a = s_alpha[n];
        size_t idx = ((size_t)b*64 + n)*256 + t;
        float h2 = (1.f - a)*s_hn[n*256 + t] + a*st;
        __half hi, lo; h_split(h2, hi, lo);
        g_hH[idx] = hi; g_hL[idx] = lo;
        if (final_) out[idx] = h2;
        accS += s_p[n] * h2;
    }
    g_star[(size_t)b*256 + t] = accS;
    if (final_) out[(size_t)Bb*Nn*Hh + (size_t)b*256 + t] = accS;
}

// ---------------- launch ------------------------------------------------------
extern "C" void kernel_launch(void* const* d_in, const int* in_sizes, int n_in,
                              void* d_out, int out_size) {
    const float* A      = (const float*)d_in[0];
    const float* hidden = (const float*)d_in[1];
    const float* mask   = (const float*)d_in[2];
    const float* w_ih   = (const float*)d_in[3];
    const float* w_hh   = (const float*)d_in[4];
    const float* b_ih   = (const float*)d_in[5];
    const float* b_hh   = (const float*)d_in[6];
    const float* b_iah  = (const float*)d_in[7];
    const float* b_oah  = (const float*)d_in[8];
    const float* W_in   = (const float*)d_in[9];
    const float* b_in   = (const float*)d_in[10];
    const float* W_out  = (const float*)d_in[11];
    const float* b_out  = (const float*)d_in[12];
    float* out = (float*)d_out;

    cudaFuncSetAttribute(gemm12_mma, cudaFuncAttributeMaxDynamicSharedMemorySize, F_SMEM);
    cudaFuncSetAttribute(gemm3_mma,  cudaFuncAttributeMaxDynamicSharedMemorySize, G3_SMEM);
    cudaFuncSetAttribute(attn,       cudaFuncAttributeMaxDynamicSharedMemorySize, ATTN_SMEM);

    setup_weights<<<1536, 256>>>(W_in, b_in, W_out, b_out, w_ih, w_hh);
    setup_A<<<4096, 256>>>(A);
    init_h<<<Bb, 256>>>(hidden, mask);

    for (int s = 0; s < 2; s++) {
        gemm12_mma<<<dim3(Bb, 2), 256, F_SMEM>>>(b_iah, b_oah);
        gemm3_mma<<<dim3(8, 1024), 256, G3_SMEM>>>(b_ih, b_hh);
        attn<<<Bb, 256, ATTN_SMEM>>>(mask, out, s == 1);
    }
}

// round 13
// speedup vs baseline: 1.3307x; 1.0064x over previous
#include <cuda_runtime.h>
#include <cuda_fp16.h>
#include <math.h>
#include <cstdint>

#define Bb   2048
#define Nn   64
#define Hh   256
#define MTOT (Bb*Nn)          // 131072

// ---------------- scratch (static device globals; no allocations) ----------
__device__ float g_hn  [MTOT*Hh];
__device__ float g_star[Bb*Hh];
__device__ float g_bias1[512];
__device__ __half g_hH  [MTOT*256];
__device__ __half g_hL  [MTOT*256];       // epilogue-only
__device__ __half g_inpH[MTOT*512];
__device__ __half g_AH  [Bb*64*128];
__device__ __half g_AL  [Bb*64*128];
__device__ __half g_w1  [512*256];        // [c][k]
__device__ __half g_wih [768*512];
__device__ __half g_whh [768*256];

// ---------------- helpers ----------------------------------------------------
__device__ __forceinline__ uint32_t smem_u32(const void* p) {
    uint32_t a;
    asm("{ .reg .u64 t; cvta.to.shared.u64 t, %1; cvt.u32.u64 %0, t; }"
        : "=r"(a) : "l"(p));
    return a;
}
__device__ __forceinline__ void cp16(uint32_t dst, const void* src) {
    asm volatile("cp.async.cg.shared.global [%0], [%1], 16;"
                 :: "r"(dst), "l"(src) : "memory");
}
#define CP_COMMIT() asm volatile("cp.async.commit_group;" ::: "memory")
#define CP_WAIT(n)  asm volatile("cp.async.wait_group %0;" :: "n"(n) : "memory")

__device__ __forceinline__ void ldsm_x4(uint32_t& r0, uint32_t& r1,
                                        uint32_t& r2, uint32_t& r3,
                                        uint32_t addr) {
    asm volatile("ldmatrix.sync.aligned.m8n8.x4.shared.b16 {%0,%1,%2,%3}, [%4];"
                 : "=r"(r0), "=r"(r1), "=r"(r2), "=r"(r3) : "r"(addr));
}
__device__ __forceinline__ void ldsm_x4_t(uint32_t& r0, uint32_t& r1,
                                          uint32_t& r2, uint32_t& r3,
                                          uint32_t addr) {
    asm volatile("ldmatrix.sync.aligned.m8n8.x4.trans.shared.b16 {%0,%1,%2,%3}, [%4];"
                 : "=r"(r0), "=r"(r1), "=r"(r2), "=r"(r3) : "r"(addr));
}
__device__ __forceinline__ void mma_f16(float* d,
                                        uint32_t a0, uint32_t a1,
                                        uint32_t a2, uint32_t a3,
                                        uint32_t b0, uint32_t b1) {
    asm volatile(
        "mma.sync.aligned.m16n8k16.row.col.f32.f16.f16.f32 "
        "{%0,%1,%2,%3}, {%4,%5,%6,%7}, {%8,%9}, {%0,%1,%2,%3};"
        : "+f"(d[0]), "+f"(d[1]), "+f"(d[2]), "+f"(d[3])
        : "r"(a0), "r"(a1), "r"(a2), "r"(a3), "r"(b0), "r"(b1));
}
__device__ __forceinline__ void h_split(float v, __half& hi, __half& lo) {
    hi = __float2half_rn(v);
    lo = __float2half_rn(v - __half2float(hi));
}

// ---------------- setup -------------------------------------------------------
__global__ void setup_weights(const float* __restrict__ W_in,
                              const float* __restrict__ b_in,
                              const float* __restrict__ W_out,
                              const float* __restrict__ b_out,
                              const float* __restrict__ w_ih,
                              const float* __restrict__ w_hh) {
    int i = blockIdx.x * blockDim.x + threadIdx.x;
    if (i < 512) g_bias1[i] = (i < 256) ? b_in[i] : b_out[i-256];
    if (i < 512*256) {
        int c = i >> 8, k = i & 255;
        float v = (c < 256) ? W_in[c*256 + k] : W_out[(c-256)*256 + k];
        g_w1[i] = __float2half_rn(v);
    }
    if (i < 768*512) g_wih[i] = __float2half_rn(w_ih[i]);
    if (i < 768*256) g_whh[i] = __float2half_rn(w_hh[i]);
}

__global__ void setup_A(const float* __restrict__ A) {
    size_t n = (size_t)Bb*64*128;
    for (size_t i = blockIdx.x*(size_t)blockDim.x + threadIdx.x; i < n;
         i += (size_t)gridDim.x*blockDim.x) {
        __half hi, lo; h_split(A[i], hi, lo);
        g_AH[i] = hi; g_AL[i] = lo;
    }
}

__global__ void __launch_bounds__(256) init_h(const float* __restrict__ hidden,
                                              const float* __restrict__ mask) {
    int b = blockIdx.x, t = threadIdx.x;
    float len = 0.f, acc = 0.f;
#pragma unroll 4
    for (int n = 0; n < 64; n++) {
        float mk = mask[b*64 + n];
        size_t idx = ((size_t)b*64 + n)*256 + t;
        float v = hidden[idx];
        __half hi, lo; h_split(v, hi, lo);
        g_hH[idx] = hi; g_hL[idx] = lo;
        acc += v * mk; len += mk;
    }
    g_star[(size_t)b*256 + t] = acc / len;
}

// ---------------- FUSED GEMM1+GEMM2 (unchanged from R12) ----------------------
#define F_H    0
#define F_W    33792
#define F_A    74752
#define F_SMEM 93184

__device__ __forceinline__ void f_load_w1(uint32_t sbase, int st, int ch, int half_) {
    const int t = threadIdx.x;
    uint32_t sb = sbase + F_W + st*20480;
#pragma unroll
    for (int f = 0; f < 4; f++) {
        int u = f*256 + t; int row = u >> 2, seg = u & 3;
        cp16(sb + row*80 + seg*16,
             g_w1 + (size_t)(half_*256 + row)*256 + ch*32 + seg*8);
    }
}

__global__ void __launch_bounds__(256, 2) gemm12_mma(const float* __restrict__ b_iah,
                                                     const float* __restrict__ b_oah) {
    extern __shared__ __align__(16) char smem[];
    const int t = threadIdx.x, wid = t >> 5, lane = t & 31;
    const int b = blockIdx.x, half_ = blockIdx.y;
    const int wr = wid >> 2, wc = wid & 3;
    uint32_t sbase = smem_u32(smem);

#pragma unroll
    for (int f = 0; f < 8; f++) {
        int u = f*256 + t; int row = u >> 5, seg = u & 31;
        cp16(sbase + F_H + row*528 + seg*16,
             g_hH + ((size_t)b*64 + row)*256 + seg*8);
    }
#pragma unroll
    for (int f = 0; f < 4; f++) {
        int u = f*256 + t; int pl = u >> 9, row = (u >> 3) & 63, seg = u & 7;
        const __half* src = pl ? g_AL : g_AH;
        cp16(sbase + F_A + pl*9216 + row*144 + seg*16,
             src + (size_t)b*8192 + row*128 + half_*64 + seg*8);
    }
    CP_COMMIT();
    f_load_w1(sbase, 0, 0, half_);
    CP_COMMIT();

    const int midx = lane >> 3;
    const int trow = (midx >> 1)*8 + (lane & 7);
    const int kh   = (midx & 1)*16;

    // ---- phase 1 ----
    {
        float acc[8][2][4];
#pragma unroll
        for (int cf = 0; cf < 8; cf++)
#pragma unroll
            for (int r = 0; r < 2; r++)
#pragma unroll
                for (int i = 0; i < 4; i++) acc[cf][r][i] = 0.f;

        const uint32_t aRow0 = sbase + F_H + (wr*32 + (lane & 15))*528 +
                               (lane >> 4)*16;
        for (int ch = 0; ch < 8; ch++) {
            if (ch + 1 < 8) {
                f_load_w1(sbase, (ch + 1) & 1, ch + 1, half_);
                CP_COMMIT();
                CP_WAIT(1);
            } else {
                CP_WAIT(0);
            }
            __syncthreads();
            uint32_t sbW = sbase + F_W + (ch & 1)*20480;
#pragma unroll
            for (int kt = 0; kt < 2; kt++) {
                uint32_t a[2][4];
#pragma unroll
                for (int r = 0; r < 2; r++)
                    ldsm_x4(a[r][0], a[r][1], a[r][2], a[r][3],
                            aRow0 + r*16*528 + ch*64 + kt*32);
#pragma unroll
                for (int cf4 = 0; cf4 < 4; cf4++) {
                    uint32_t ba = sbW + (wc*64 + cf4*16 + trow)*80 + kt*32 + kh;
                    uint32_t b0, b1, b2, b3;
                    ldsm_x4(b0, b1, b2, b3, ba);
#pragma unroll
                    for (int r = 0; r < 2; r++) {
                        mma_f16(acc[cf4*2][r],   a[r][0], a[r][1], a[r][2], a[r][3], b0, b1);
                        mma_f16(acc[cf4*2+1][r], a[r][0], a[r][1], a[r][2], a[r][3], b2, b3);
                    }
                }
            }
            __syncthreads();
        }
        const int r0 = wr*32 + (lane >> 2);
        const int cb = (lane & 3)*2;
#pragma unroll
        for (int cf = 0; cf < 8; cf++) {
            int c  = wc*64 + cf*8 + cb;
            float2 bz = *(const float2*)&g_bias1[half_*256 + c];
#pragma unroll
            for (int r = 0; r < 2; r++) {
#pragma unroll
                for (int hrow = 0; hrow < 2; hrow++) {
                    int row = r0 + r*16 + hrow*8;
                    float v0 = acc[cf][r][hrow*2]   + bz.x;
                    float v1 = acc[cf][r][hrow*2+1] + bz.y;
                    *(__half2*)(smem + F_W + row*528 + c*2) =
                        __halves2half2(__float2half_rn(v0), __float2half_rn(v1));
                }
            }
        }
    }
    __syncthreads();

    // ---- phase 2 ----
    {
        float acc[2][8][4];
#pragma unroll
        for (int r = 0; r < 2; r++)
#pragma unroll
            for (int j = 0; j < 8; j++)
#pragma unroll
                for (int i = 0; i < 4; i++) acc[r][j][i] = 0.f;

        uint32_t aBase = sbase + F_A + (wr*32 + (lane & 15))*144 + (lane >> 4)*16;
#pragma unroll
        for (int kt = 0; kt < 4; kt++) {
            uint32_t ah[2][4], al[2][4];
#pragma unroll
            for (int r = 0; r < 2; r++) {
                ldsm_x4(ah[r][0], ah[r][1], ah[r][2], ah[r][3],
                        aBase + r*2304 + kt*32);
                ldsm_x4(al[r][0], al[r][1], al[r][2], al[r][3],
                        aBase + 9216 + r*2304 + kt*32);
            }
#pragma unroll
            for (int jj = 0; jj < 4; jj++) {
                uint32_t ba = sbase + F_W + (kt*16 + (lane & 15))*528 +
                              (wc*64 + jj*16 + (lane >> 4)*8)*2;
                uint32_t bh0, bh1, bh2, bh3;
                ldsm_x4_t(bh0, bh1, bh2, bh3, ba);
#pragma unroll
                for (int r = 0; r < 2; r++) {
                    mma_f16(acc[r][jj*2],   ah[r][0], ah[r][1], ah[r][2], ah[r][3], bh0, bh1);
                    mma_f16(acc[r][jj*2+1], ah[r][0], ah[r][1], ah[r][2], ah[r][3], bh2, bh3);
                    mma_f16(acc[r][jj*2],   al[r][0], al[r][1], al[r][2], al[r][3], bh0, bh1);
                    mma_f16(acc[r][jj*2+1], al[r][0], al[r][1], al[r][2], al[r][3], bh2, bh3);
                }
            }
        }
        const float* bias = half_ ? b_oah : b_iah;
#pragma unroll
        for (int r = 0; r < 2; r++) {
            int n = wr*32 + r*16 + (lane >> 2);
#pragma unroll
            for (int j = 0; j < 8; j++) {
                int col = wc*64 + j*8 + (lane & 3)*2;
#pragma unroll
                for (int hrow = 0; hrow < 2; hrow++) {
                    int nn = n + hrow*8;
                    float v0 = acc[r][j][hrow*2]   + bias[col];
                    float v1 = acc[r][j][hrow*2+1] + bias[col+1];
                    size_t o = ((size_t)b*64 + nn)*512 + half_*256 + col;
                    *(__half2*)&g_inpH[o] =
                        __halves2half2(__float2half_rn(v0), __float2half_rn(v1));
                }
            }
        }
    }
}

// ---------------- GEMM3: 3-stage pipeline, one sync per chunk ------------------
#define G3_B     18432
#define G3_STAGE 32256
#define G3_BIAS  (3*G3_STAGE)     // 96768
#define G3_SMEM  (G3_BIAS + 768)  // 97536

__device__ __forceinline__ void g3_load(uint32_t sbase, int st, int ch,
                                        int m0, int c0) {
    const int t = threadIdx.x;
    uint32_t sb = sbase + st*G3_STAGE;
    const __half *Ah, *Bw; int ak, koff;
    if (ch < 8) { Ah = g_inpH; Bw = g_wih; ak = 512; koff = ch*64; }
    else        { Ah = g_hH;   Bw = g_whh; ak = 256; koff = (ch-8)*64; }
#pragma unroll
    for (int f = 0; f < 4; f++) {
        int u = f*256 + t; int row = u >> 3, seg = u & 7;
        cp16(sb + row*144 + seg*16,
             Ah + (size_t)(m0+row)*ak + koff + seg*8);
    }
#pragma unroll
    for (int f = 0; f < 3; f++) {
        int u = f*256 + t; int row = u >> 3, seg = u & 7;
        int g = row >> 5, n = row & 31;
        cp16(sb + G3_B + row*144 + seg*16,
             Bw + (size_t)(g*256 + c0 + n)*ak + koff + seg*8);
    }
}

template<bool GH>
__device__ __forceinline__ void g3_mma_chunk(uint32_t sb, int wr, int wc, int lane,
                                             float (&acc)[4][2][2][4]) {
    uint32_t aBase = sb + (wr*32 + (lane & 15))*144 + (lane >> 4)*16;
    const int midx = lane >> 3;
    const int trow = (midx >> 1)*8 + (lane & 7);
    const int kh   = (midx & 1)*16;
#pragma unroll
    for (int kt = 0; kt < 4; kt++) {
        uint32_t a[2][4];
#pragma unroll
        for (int r = 0; r < 2; r++)
            ldsm_x4(a[r][0], a[r][1], a[r][2], a[r][3],
                    aBase + r*2304 + kt*32);
#pragma unroll
        for (int g = 0; g < 3; g++) {
            const int p = (!GH || g < 2) ? g : 3;
            uint32_t b0, b1, b2, b3;
            ldsm_x4(b0, b1, b2, b3,
                    sb + G3_B + (g*32 + wc*16 + trow)*144 + kt*32 + kh);
#pragma unroll
            for (int r = 0; r < 2; r++) {
                mma_f16(acc[p][r][0], a[r][0], a[r][1], a[r][2], a[r][3], b0, b1);
                mma_f16(acc[p][r][1], a[r][0], a[r][1], a[r][2], a[r][3], b2, b3);
            }
        }
    }
}

__global__ void __launch_bounds__(256, 2) gemm3_mma(const float* __restrict__ b_ih,
                                                    const float* __restrict__ b_hh) {
    extern __shared__ __align__(16) char smem[];
    const int t = threadIdx.x, wid = t >> 5, lane = t & 31;
    const int c0 = blockIdx.x * 32, m0 = blockIdx.y * 128;
    const int wr = wid & 3, wc = wid >> 2;
    uint32_t sbase = smem_u32(smem);
    float* sbih = (float*)(smem + G3_BIAS);
    float* sbhh = (float*)(smem + G3_BIAS + 384);
    if (t < 32) {
#pragma unroll
        for (int g = 0; g < 3; g++) {
            sbih[g*32 + t] = b_ih[g*256 + c0 + t];
            sbhh[g*32 + t] = b_hh[g*256 + c0 + t];
        }
    }
    float acc[4][2][2][4];
#pragma unroll
    for (int p = 0; p < 4; p++)
#pragma unroll
        for (int r = 0; r < 2; r++)
#pragma unroll
            for (int cgi = 0; cgi < 2; cgi++)
#pragma unroll
                for (int i = 0; i < 4; i++) acc[p][r][cgi][i] = 0.f;

    g3_load(sbase, 0, 0, m0, c0);
    CP_COMMIT();
    g3_load(sbase, 1, 1, m0, c0);
    CP_COMMIT();

    for (int ch = 0; ch < 12; ch++) {
        if (ch < 11) { CP_WAIT(1); } else { CP_WAIT(0); }
        __syncthreads();
        if (ch + 2 < 12) {
            g3_load(sbase, (ch + 2) % 3, ch + 2, m0, c0);
            CP_COMMIT();
        }
        uint32_t sb = sbase + (ch % 3)*G3_STAGE;
        if (ch < 8) g3_mma_chunk<false>(sb, wr, wc, lane, acc);
        else        g3_mma_chunk<true >(sb, wr, wc, lane, acc);
    }

    // GRU epilogue (h reconstructed exactly from fp16 hi/lo pair)
    const int rbase = m0 + wr*32 + (lane >> 2);
    const int cb = (lane & 3)*2;
#pragma unroll
    for (int r = 0; r < 2; r++) {
#pragma unroll
        for (int cgi = 0; cgi < 2; cgi++) {
            int cl = wc*16 + cgi*8 + cb;
            int c  = c0 + cl;
#pragma unroll
            for (int hrow = 0; hrow < 2; hrow++) {
                int m = rbase + r*16 + hrow*8;
                __half2 hh = *(const __half2*)&g_hH[(size_t)m*256 + c];
                __half2 hl = *(const __half2*)&g_hL[(size_t)m*256 + c];
                float hv[2];
                hv[0] = __half2float(__low2half(hh)) + __half2float(__low2half(hl));
                hv[1] = __half2float(__high2half(hh)) + __half2float(__high2half(hl));
                float o[2];
#pragma unroll
                for (int e = 0; e < 2; e++) {
                    int li = cl + e;
                    int fi = hrow*2 + e;
                    float rr = 1.f/(1.f + expf(-(acc[0][r][cgi][fi] +
                                                 sbih[li] + sbhh[li])));
                    float zz = 1.f/(1.f + expf(-(acc[1][r][cgi][fi] +
                                                 sbih[32+li] + sbhh[32+li])));
                    float nn = tanhf(acc[2][r][cgi][fi] + sbih[64+li] +
                                     rr*(acc[3][r][cgi][fi] + sbhh[64+li]));
                    o[e] = nn + zz*(hv[e] - nn);
                }
                *(float2*)&g_hn[(size_t)m*256 + c] = make_float2(o[0], o[1]);
            }
        }
    }
}

// ---------------- attention / star update -------------------------------------
#define ATTN_SMEM ((16384 + 256 + 64 + 64 + 64) * 4)

__global__ void __launch_bounds__(256) attn(const float* __restrict__ mask,
                                            float* __restrict__ out,
                                            int final_) {
    extern __shared__ float sm[];
    float* s_hn    = sm;
    float* s_star  = sm + 16384;
    float* s_alpha = s_star + 256;
    float* s_v     = s_alpha + 64;
    float* s_p     = s_v + 64;
    int b = blockIdx.x, t = threadIdx.x, lane = t & 31, w = t >> 5;
    s_star[t] = g_star[(size_t)b*256 + t];
    const float4* src = (const float4*)&g_hn[(size_t)b*64*256];
    float4* dst = (float4*)s_hn;
#pragma unroll
    for (int f = 0; f < 16; f++) dst[f*256 + t] = src[f*256 + t];
    __syncthreads();
#pragma unroll
    for (int r = 0; r < 8; r++) {
        int n = w*8 + r;
        float p = 0.f;
#pragma unroll
        for (int j = lane; j < 256; j += 32) p += s_hn[n*256 + j] * s_star[j];
#pragma unroll
        for (int o = 16; o; o >>= 1) p += __shfl_xor_sync(0xffffffffu, p, o);
        if (lane == 0) s_v[n] = p;
    }
    __syncthreads();
    float ss = 0.f;
#pragma unroll 8
    for (int j = 0; j < 256; j++) { float x = s_star[j]; ss += x*x; }
    if (t < 64) {
        float sraw = s_v[t];
        float a = 1.f / (1.f + expf(-sraw * 0.0625f));
        s_alpha[t] = a;
        float d2 = (1.f - a)*sraw + a*ss;
        s_v[t] = expf(d2) * mask[(size_t)b*64 + t];
    }
    __syncthreads();
    float den = 1e-24f;
#pragma unroll
    for (int n = 0; n < 64; n++) den += s_v[n];
    if (t < 64) s_p[t] = s_v[t] / den;
    __syncthreads();
    float st = s_star[t];
    float accS = 0.f;
#pragma unroll 4
    for (int n = 0; n < 64; n++) {
        float a = s_alpha[n];
        size_t idx = ((size_t)b*64 + n)*256 + t;
        float h2 = (1.f - a)*s_hn[n*256 + t] + a*st;
        __half hi, lo; h_split(h2, hi, lo);
        g_hH[idx] = hi; g_hL[idx] = lo;
        if (final_) out[idx] = h2;
        accS += s_p[n] * h2;
    }
    g_star[(size_t)b*256 + t] = accS;
    if (final_) out[(size_t)Bb*Nn*Hh + (size_t)b*256 + t] = accS;
}

// ---------------- launch ------------------------------------------------------
extern "C" void kernel_launch(void* const* d_in, const int* in_sizes, int n_in,
                              void* d_out, int out_size) {
    const float* A      = (const float*)d_in[0];
    const float* hidden = (const float*)d_in[1];
    const float* mask   = (const float*)d_in[2];
    const float* w_ih   = (const float*)d_in[3];
    const float* w_hh   = (const float*)d_in[4];
    const float* b_ih   = (const float*)d_in[5];
    const float* b_hh   = (const float*)d_in[6];
    const float* b_iah  = (const float*)d_in[7];
    const float* b_oah  = (const float*)d_in[8];
    const float* W_in   = (const float*)d_in[9];
    const float* b_in   = (const float*)d_in[10];
    const float* W_out  = (const float*)d_in[11];
    const float* b_out  = (const float*)d_in[12];
    float* out = (float*)d_out;

    cudaFuncSetAttribute(gemm12_mma, cudaFuncAttributeMaxDynamicSharedMemorySize, F_SMEM);
    cudaFuncSetAttribute(gemm3_mma,  cudaFuncAttributeMaxDynamicSharedMemorySize, G3_SMEM);
    cudaFuncSetAttribute(attn,       cudaFuncAttributeMaxDynamicSharedMemorySize, ATTN_SMEM);

    setup_weights<<<1536, 256>>>(W_in, b_in, W_out, b_out, w_ih, w_hh);
    setup_A<<<4096, 256>>>(A);
    init_h<<<Bb, 256>>>(hidden, mask);

    for (int s = 0; s < 2; s++) {
        gemm12_mma<<<dim3(Bb, 2), 256, F_SMEM>>>(b_iah, b_oah);
        gemm3_mma<<<dim3(8, 1024), 256, G3_SMEM>>>(b_ih, b_hh);
        attn<<<Bb, 256, ATTN_SMEM>>>(mask, out, s == 1);
    }
}

// round 14
// speedup vs baseline: 1.3595x; 1.0217x over previous
#include <cuda_runtime.h>
#include <cuda_fp16.h>
#include <math.h>
#include <cstdint>

#define Bb   2048
#define Nn   64
#define Hh   256
#define MTOT (Bb*Nn)          // 131072

// ---------------- scratch (static device globals; no allocations) ----------
__device__ float g_hn  [MTOT*Hh];
__device__ float g_star[Bb*Hh];
__device__ float g_bias1[512];
__device__ __half g_hH  [MTOT*256];
__device__ __half g_hL  [MTOT*256];       // epilogue-only
__device__ __half g_inpH[MTOT*512];
__device__ __half g_AH  [Bb*64*128];
__device__ __half g_w1  [512*256];        // [c][k]
__device__ __half g_wih [768*512];
__device__ __half g_whh [768*256];

// ---------------- helpers ----------------------------------------------------
__device__ __forceinline__ uint32_t smem_u32(const void* p) {
    uint32_t a;
    asm("{ .reg .u64 t; cvta.to.shared.u64 t, %1; cvt.u32.u64 %0, t; }"
        : "=r"(a) : "l"(p));
    return a;
}
__device__ __forceinline__ void cp16(uint32_t dst, const void* src) {
    asm volatile("cp.async.cg.shared.global [%0], [%1], 16;"
                 :: "r"(dst), "l"(src) : "memory");
}
#define CP_COMMIT() asm volatile("cp.async.commit_group;" ::: "memory")
#define CP_WAIT(n)  asm volatile("cp.async.wait_group %0;" :: "n"(n) : "memory")

__device__ __forceinline__ void ldsm_x4(uint32_t& r0, uint32_t& r1,
                                        uint32_t& r2, uint32_t& r3,
                                        uint32_t addr) {
    asm volatile("ldmatrix.sync.aligned.m8n8.x4.shared.b16 {%0,%1,%2,%3}, [%4];"
                 : "=r"(r0), "=r"(r1), "=r"(r2), "=r"(r3) : "r"(addr));
}
__device__ __forceinline__ void ldsm_x4_t(uint32_t& r0, uint32_t& r1,
                                          uint32_t& r2, uint32_t& r3,
                                          uint32_t addr) {
    asm volatile("ldmatrix.sync.aligned.m8n8.x4.trans.shared.b16 {%0,%1,%2,%3}, [%4];"
                 : "=r"(r0), "=r"(r1), "=r"(r2), "=r"(r3) : "r"(addr));
}
__device__ __forceinline__ void mma_f16(float* d,
                                        uint32_t a0, uint32_t a1,
                                        uint32_t a2, uint32_t a3,
                                        uint32_t b0, uint32_t b1) {
    asm volatile(
        "mma.sync.aligned.m16n8k16.row.col.f32.f16.f16.f32 "
        "{%0,%1,%2,%3}, {%4,%5,%6,%7}, {%8,%9}, {%0,%1,%2,%3};"
        : "+f"(d[0]), "+f"(d[1]), "+f"(d[2]), "+f"(d[3])
        : "r"(a0), "r"(a1), "r"(a2), "r"(a3), "r"(b0), "r"(b1));
}
__device__ __forceinline__ void h_split(float v, __half& hi, __half& lo) {
    hi = __float2half_rn(v);
    lo = __float2half_rn(v - __half2float(hi));
}

// ---------------- setup -------------------------------------------------------
__global__ void setup_weights(const float* __restrict__ W_in,
                              const float* __restrict__ b_in,
                              const float* __restrict__ W_out,
                              const float* __restrict__ b_out,
                              const float* __restrict__ w_ih,
                              const float* __restrict__ w_hh) {
    int i = blockIdx.x * blockDim.x + threadIdx.x;
    if (i < 512) g_bias1[i] = (i < 256) ? b_in[i] : b_out[i-256];
    if (i < 512*256) {
        int c = i >> 8, k = i & 255;
        float v = (c < 256) ? W_in[c*256 + k] : W_out[(c-256)*256 + k];
        g_w1[i] = __float2half_rn(v);
    }
    if (i < 768*512) g_wih[i] = __float2half_rn(w_ih[i]);
    if (i < 768*256) g_whh[i] = __float2half_rn(w_hh[i]);
}

__global__ void setup_A(const float* __restrict__ A) {
    size_t n = (size_t)Bb*64*128;
    for (size_t i = blockIdx.x*(size_t)blockDim.x + threadIdx.x; i < n;
         i += (size_t)gridDim.x*blockDim.x)
        g_AH[i] = __float2half_rn(A[i]);
}

__global__ void __launch_bounds__(256) init_h(const float* __restrict__ hidden,
                                              const float* __restrict__ mask) {
    int b = blockIdx.x, t = threadIdx.x;
    float len = 0.f, acc = 0.f;
#pragma unroll 4
    for (int n = 0; n < 64; n++) {
        float mk = mask[b*64 + n];
        size_t idx = ((size_t)b*64 + n)*256 + t;
        float v = hidden[idx];
        __half hi, lo; h_split(v, hi, lo);
        g_hH[idx] = hi; g_hL[idx] = lo;
        acc += v * mk; len += mk;
    }
    g_star[(size_t)b*256 + t] = acc / len;
}

// ---------------- FUSED GEMM1+GEMM2 -------------------------------------------
// smem: h 64x528=33792 | w1 2x20480=40960 (hio 64x528 overlays) | A 9216
#define F_H    0
#define F_W    33792
#define F_A    74752
#define F_SMEM 83968

__device__ __forceinline__ void f_load_w1(uint32_t sbase, int st, int ch, int half_) {
    const int t = threadIdx.x;
    uint32_t sb = sbase + F_W + st*20480;
#pragma unroll
    for (int f = 0; f < 4; f++) {
        int u = f*256 + t; int row = u >> 2, seg = u & 3;
        cp16(sb + row*80 + seg*16,
             g_w1 + (size_t)(half_*256 + row)*256 + ch*32 + seg*8);
    }
}

__global__ void __launch_bounds__(256, 2) gemm12_mma(const float* __restrict__ b_iah,
                                                     const float* __restrict__ b_oah) {
    extern __shared__ __align__(16) char smem[];
    const int t = threadIdx.x, wid = t >> 5, lane = t & 31;
    const int b = blockIdx.x, half_ = blockIdx.y;
    const int wr = wid >> 2, wc = wid & 3;
    uint32_t sbase = smem_u32(smem);

    // h tile + adjacency tile (hi only)
#pragma unroll
    for (int f = 0; f < 8; f++) {
        int u = f*256 + t; int row = u >> 5, seg = u & 31;
        cp16(sbase + F_H + row*528 + seg*16,
             g_hH + ((size_t)b*64 + row)*256 + seg*8);
    }
#pragma unroll
    for (int f = 0; f < 2; f++) {
        int u = f*256 + t; int row = u >> 3, seg = u & 7;
        cp16(sbase + F_A + row*144 + seg*16,
             g_AH + (size_t)b*8192 + row*128 + half_*64 + seg*8);
    }
    f_load_w1(sbase, 0, 0, half_);
    CP_COMMIT();

    const int midx = lane >> 3;
    const int trow = (midx >> 1)*8 + (lane & 7);
    const int kh   = (midx & 1)*16;

    // ---- phase 1: hio = h @ w1_half^T (single sync per chunk, 2-stage) ----
    {
        float acc[8][2][4];
#pragma unroll
        for (int cf = 0; cf < 8; cf++)
#pragma unroll
            for (int r = 0; r < 2; r++)
#pragma unroll
                for (int i = 0; i < 4; i++) acc[cf][r][i] = 0.f;

        const uint32_t aRow0 = sbase + F_H + (wr*32 + (lane & 15))*528 +
                               (lane >> 4)*16;
        for (int ch = 0; ch < 8; ch++) {
            CP_WAIT(0);
            __syncthreads();
            if (ch + 1 < 8) {
                f_load_w1(sbase, (ch + 1) & 1, ch + 1, half_);
                CP_COMMIT();
            }
            uint32_t sbW = sbase + F_W + (ch & 1)*20480;
#pragma unroll
            for (int kt = 0; kt < 2; kt++) {
                uint32_t a[2][4];
#pragma unroll
                for (int r = 0; r < 2; r++)
                    ldsm_x4(a[r][0], a[r][1], a[r][2], a[r][3],
                            aRow0 + r*16*528 + ch*64 + kt*32);
#pragma unroll
                for (int cf4 = 0; cf4 < 4; cf4++) {
                    uint32_t ba = sbW + (wc*64 + cf4*16 + trow)*80 + kt*32 + kh;
                    uint32_t b0, b1, b2, b3;
                    ldsm_x4(b0, b1, b2, b3, ba);
#pragma unroll
                    for (int r = 0; r < 2; r++) {
                        mma_f16(acc[cf4*2][r],   a[r][0], a[r][1], a[r][2], a[r][3], b0, b1);
                        mma_f16(acc[cf4*2+1][r], a[r][0], a[r][1], a[r][2], a[r][3], b2, b3);
                    }
                }
            }
        }
        __syncthreads();   // all warps done reading w1 stages before hio overlays
        const int r0 = wr*32 + (lane >> 2);
        const int cb = (lane & 3)*2;
#pragma unroll
        for (int cf = 0; cf < 8; cf++) {
            int c  = wc*64 + cf*8 + cb;
            float2 bz = *(const float2*)&g_bias1[half_*256 + c];
#pragma unroll
            for (int r = 0; r < 2; r++) {
#pragma unroll
                for (int hrow = 0; hrow < 2; hrow++) {
                    int row = r0 + r*16 + hrow*8;
                    float v0 = acc[cf][r][hrow*2]   + bz.x;
                    float v1 = acc[cf][r][hrow*2+1] + bz.y;
                    *(__half2*)(smem + F_W + row*528 + c*2) =
                        __halves2half2(__float2half_rn(v0), __float2half_rn(v1));
                }
            }
        }
    }
    __syncthreads();

    // ---- phase 2: inp = A_adj @ hio + bias (A hi only) ----
    {
        float acc[2][8][4];
#pragma unroll
        for (int r = 0; r < 2; r++)
#pragma unroll
            for (int j = 0; j < 8; j++)
#pragma unroll
                for (int i = 0; i < 4; i++) acc[r][j][i] = 0.f;

        uint32_t aBase = sbase + F_A + (wr*32 + (lane & 15))*144 + (lane >> 4)*16;
#pragma unroll
        for (int kt = 0; kt < 4; kt++) {
            uint32_t ah[2][4];
#pragma unroll
            for (int r = 0; r < 2; r++)
                ldsm_x4(ah[r][0], ah[r][1], ah[r][2], ah[r][3],
                        aBase + r*2304 + kt*32);
#pragma unroll
            for (int jj = 0; jj < 4; jj++) {
                uint32_t ba = sbase + F_W + (kt*16 + (lane & 15))*528 +
                              (wc*64 + jj*16 + (lane >> 4)*8)*2;
                uint32_t bh0, bh1, bh2, bh3;
                ldsm_x4_t(bh0, bh1, bh2, bh3, ba);
#pragma unroll
                for (int r = 0; r < 2; r++) {
                    mma_f16(acc[r][jj*2],   ah[r][0], ah[r][1], ah[r][2], ah[r][3], bh0, bh1);
                    mma_f16(acc[r][jj*2+1], ah[r][0], ah[r][1], ah[r][2], ah[r][3], bh2, bh3);
                }
            }
        }
        const float* bias = half_ ? b_oah : b_iah;
#pragma unroll
        for (int r = 0; r < 2; r++) {
            int n = wr*32 + r*16 + (lane >> 2);
#pragma unroll
            for (int j = 0; j < 8; j++) {
                int col = wc*64 + j*8 + (lane & 3)*2;
#pragma unroll
                for (int hrow = 0; hrow < 2; hrow++) {
                    int nn = n + hrow*8;
                    float v0 = acc[r][j][hrow*2]   + bias[col];
                    float v1 = acc[r][j][hrow*2+1] + bias[col+1];
                    size_t o = ((size_t)b*64 + nn)*512 + half_*256 + col;
                    *(__half2*)&g_inpH[o] =
                        __halves2half2(__float2half_rn(v0), __float2half_rn(v1));
                }
            }
        }
    }
}

// ---------------- GEMM3: 3-stage pipeline, one sync per chunk ------------------
#define G3_B     18432
#define G3_STAGE 32256
#define G3_BIAS  (3*G3_STAGE)     // 96768
#define G3_SMEM  (G3_BIAS + 768)  // 97536

__device__ __forceinline__ void g3_load(uint32_t sbase, int st, int ch,
                                        int m0, int c0) {
    const int t = threadIdx.x;
    uint32_t sb = sbase + st*G3_STAGE;
    const __half *Ah, *Bw; int ak, koff;
    if (ch < 8) { Ah = g_inpH; Bw = g_wih; ak = 512; koff = ch*64; }
    else        { Ah = g_hH;   Bw = g_whh; ak = 256; koff = (ch-8)*64; }
#pragma unroll
    for (int f = 0; f < 4; f++) {
        int u = f*256 + t; int row = u >> 3, seg = u & 7;
        cp16(sb + row*144 + seg*16,
             Ah + (size_t)(m0+row)*ak + koff + seg*8);
    }
#pragma unroll
    for (int f = 0; f < 3; f++) {
        int u = f*256 + t; int row = u >> 3, seg = u & 7;
        int g = row >> 5, n = row & 31;
        cp16(sb + G3_B + row*144 + seg*16,
             Bw + (size_t)(g*256 + c0 + n)*ak + koff + seg*8);
    }
}

template<bool GH>
__device__ __forceinline__ void g3_mma_chunk(uint32_t sb, int wr, int wc, int lane,
                                             float (&acc)[4][2][2][4]) {
    uint32_t aBase = sb + (wr*32 + (lane & 15))*144 + (lane >> 4)*16;
    const int midx = lane >> 3;
    const int trow = (midx >> 1)*8 + (lane & 7);
    const int kh   = (midx & 1)*16;
#pragma unroll
    for (int kt = 0; kt < 4; kt++) {
        uint32_t a[2][4];
#pragma unroll
        for (int r = 0; r < 2; r++)
            ldsm_x4(a[r][0], a[r][1], a[r][2], a[r][3],
                    aBase + r*2304 + kt*32);
#pragma unroll
        for (int g = 0; g < 3; g++) {
            const int p = (!GH || g < 2) ? g : 3;
            uint32_t b0, b1, b2, b3;
            ldsm_x4(b0, b1, b2, b3,
                    sb + G3_B + (g*32 + wc*16 + trow)*144 + kt*32 + kh);
#pragma unroll
            for (int r = 0; r < 2; r++) {
                mma_f16(acc[p][r][0], a[r][0], a[r][1], a[r][2], a[r][3], b0, b1);
                mma_f16(acc[p][r][1], a[r][0], a[r][1], a[r][2], a[r][3], b2, b3);
            }
        }
    }
}

__global__ void __launch_bounds__(256, 2) gemm3_mma(const float* __restrict__ b_ih,
                                                    const float* __restrict__ b_hh) {
    extern __shared__ __align__(16) char smem[];
    const int t = threadIdx.x, wid = t >> 5, lane = t & 31;
    const int c0 = blockIdx.x * 32, m0 = blockIdx.y * 128;
    const int wr = wid & 3, wc = wid >> 2;
    uint32_t sbase = smem_u32(smem);
    float* sbih = (float*)(smem + G3_BIAS);
    float* sbhh = (float*)(smem + G3_BIAS + 384);
    if (t < 32) {
#pragma unroll
        for (int g = 0; g < 3; g++) {
            sbih[g*32 + t] = b_ih[g*256 + c0 + t];
            sbhh[g*32 + t] = b_hh[g*256 + c0 + t];
        }
    }
    float acc[4][2][2][4];
#pragma unroll
    for (int p = 0; p < 4; p++)
#pragma unroll
        for (int r = 0; r < 2; r++)
#pragma unroll
            for (int cgi = 0; cgi < 2; cgi++)
#pragma unroll
                for (int i = 0; i < 4; i++) acc[p][r][cgi][i] = 0.f;

    g3_load(sbase, 0, 0, m0, c0);
    CP_COMMIT();
    g3_load(sbase, 1, 1, m0, c0);
    CP_COMMIT();

    for (int ch = 0; ch < 12; ch++) {
        if (ch < 11) { CP_WAIT(1); } else { CP_WAIT(0); }
        __syncthreads();
        if (ch + 2 < 12) {
            g3_load(sbase, (ch + 2) % 3, ch + 2, m0, c0);
            CP_COMMIT();
        }
        uint32_t sb = sbase + (ch % 3)*G3_STAGE;
        if (ch < 8) g3_mma_chunk<false>(sb, wr, wc, lane, acc);
        else        g3_mma_chunk<true >(sb, wr, wc, lane, acc);
    }

    // GRU epilogue (h reconstructed exactly from fp16 hi/lo pair)
    const int rbase = m0 + wr*32 + (lane >> 2);
    const int cb = (lane & 3)*2;
#pragma unroll
    for (int r = 0; r < 2; r++) {
#pragma unroll
        for (int cgi = 0; cgi < 2; cgi++) {
            int cl = wc*16 + cgi*8 + cb;
            int c  = c0 + cl;
#pragma unroll
            for (int hrow = 0; hrow < 2; hrow++) {
                int m = rbase + r*16 + hrow*8;
                __half2 hh = *(const __half2*)&g_hH[(size_t)m*256 + c];
                __half2 hl = *(const __half2*)&g_hL[(size_t)m*256 + c];
                float hv[2];
                hv[0] = __half2float(__low2half(hh)) + __half2float(__low2half(hl));
                hv[1] = __half2float(__high2half(hh)) + __half2float(__high2half(hl));
                float o[2];
#pragma unroll
                for (int e = 0; e < 2; e++) {
                    int li = cl + e;
                    int fi = hrow*2 + e;
                    float rr = 1.f/(1.f + expf(-(acc[0][r][cgi][fi] +
                                                 sbih[li] + sbhh[li])));
                    float zz = 1.f/(1.f + expf(-(acc[1][r][cgi][fi] +
                                                 sbih[32+li] + sbhh[32+li])));
                    float nn = tanhf(acc[2][r][cgi][fi] + sbih[64+li] +
                                     rr*(acc[3][r][cgi][fi] + sbhh[64+li]));
                    o[e] = nn + zz*(hv[e] - nn);
                }
                *(float2*)&g_hn[(size_t)m*256 + c] = make_float2(o[0], o[1]);
            }
        }
    }
}

// ---------------- attention / star update -------------------------------------
#define ATTN_SMEM ((16384 + 256 + 64 + 64 + 64) * 4)

__global__ void __launch_bounds__(256) attn(const float* __restrict__ mask,
                                            float* __restrict__ out,
                                            int final_) {
    extern __shared__ float sm[];
    float* s_hn    = sm;
    float* s_star  = sm + 16384;
    float* s_alpha = s_star + 256;
    float* s_v     = s_alpha + 64;
    float* s_p     = s_v + 64;
    int b = blockIdx.x, t = threadIdx.x, lane = t & 31, w = t >> 5;
    s_star[t] = g_star[(size_t)b*256 + t];
    const float4* src = (const float4*)&g_hn[(size_t)b*64*256];
    float4* dst = (float4*)s_hn;
#pragma unroll
    for (int f = 0; f < 16; f++) dst[f*256 + t] = src[f*256 + t];
    __syncthreads();
#pragma unroll
    for (int r = 0; r < 8; r++) {
        int n = w*8 + r;
        float p = 0.f;
#pragma unroll
        for (int j = lane; j < 256; j += 32) p += s_hn[n*256 + j] * s_star[j];
#pragma unroll
        for (int o = 16; o; o >>= 1) p += __shfl_xor_sync(0xffffffffu, p, o);
        if (lane == 0) s_v[n] = p;
    }
    __syncthreads();
    float ss = 0.f;
#pragma unroll 8
    for (int j = 0; j < 256; j++) { float x = s_star[j]; ss += x*x; }
    if (t < 64) {
        float sraw = s_v[t];
        float a = 1.f / (1.f + expf(-sraw * 0.0625f));
        s_alpha[t] = a;
        float d2 = (1.f - a)*sraw + a*ss;
        s_v[t] = expf(d2) * mask[(size_t)b*64 + t];
    }
    __syncthreads();
    float den = 1e-24f;
#pragma unroll
    for (int n = 0; n < 64; n++) den += s_v[n];
    if (t < 64) s_p[t] = s_v[t] / den;
    __syncthreads();
    float st = s_star[t];
    float accS = 0.f;
#pragma unroll 4
    for (int n = 0; n < 64; n++) {
        float a = s_alpha[n];
        size_t idx = ((size_t)b*64 + n)*256 + t;
        float h2 = (1.f - a)*s_hn[n*256 + t] + a*st;
        __half hi, lo; h_split(h2, hi, lo);
        g_hH[idx] = hi; g_hL[idx] = lo;
        if (final_) out[idx] = h2;
        accS += s_p[n] * h2;
    }
    g_star[(size_t)b*256 + t] = accS;
    if (final_) out[(size_t)Bb*Nn*Hh + (size_t)b*256 + t] = accS;
}

// ---------------- launch ------------------------------------------------------
extern "C" void kernel_launch(void* const* d_in, const int* in_sizes, int n_in,
                              void* d_out, int out_size) {
    const float* A      = (const float*)d_in[0];
    const float* hidden = (const float*)d_in[1];
    const float* mask   = (const float*)d_in[2];
    const float* w_ih   = (const float*)d_in[3];
    const float* w_hh   = (const float*)d_in[4];
    const float* b_ih   = (const float*)d_in[5];
    const float* b_hh   = (const float*)d_in[6];
    const float* b_iah  = (const float*)d_in[7];
    const float* b_oah  = (const float*)d_in[8];
    const float* W_in   = (const float*)d_in[9];
    const float* b_in   = (const float*)d_in[10];
    const float* W_out  = (const float*)d_in[11];
    const float* b_out  = (const float*)d_in[12];
    float* out = (float*)d_out;

    cudaFuncSetAttribute(gemm12_mma, cudaFuncAttributeMaxDynamicSharedMemorySize, F_SMEM);
    cudaFuncSetAttribute(gemm3_mma,  cudaFuncAttributeMaxDynamicSharedMemorySize, G3_SMEM);
    cudaFuncSetAttribute(attn,       cudaFuncAttributeMaxDynamicSharedMemorySize, ATTN_SMEM);

    setup_weights<<<1536, 256>>>(W_in, b_in, W_out, b_out, w_ih, w_hh);
    setup_A<<<4096, 256>>>(A);
    init_h<<<Bb, 256>>>(hidden, mask);

    for (int s = 0; s < 2; s++) {
        gemm12_mma<<<dim3(Bb, 2), 256, F_SMEM>>>(b_iah, b_oah);
        gemm3_mma<<<dim3(8, 1024), 256, G3_SMEM>>>(b_ih, b_hh);
        attn<<<Bb, 256, ATTN_SMEM>>>(mask, out, s == 1);
    }
}

// round 16
// speedup vs baseline: 1.4125x; 1.0389x over previous
#include <cuda_runtime.h>
#include <cuda_fp16.h>
#include <math.h>
#include <cstdint>

#define Bb   2048
#define Nn   64
#define Hh   256
#define MTOT (Bb*Nn)          // 131072

// ---------------- scratch (static device globals; no allocations) ----------
__device__ float g_hn  [MTOT*Hh];
__device__ float g_star[Bb*Hh];
__device__ float g_bias1[512];
__device__ __half g_hH  [MTOT*256];
__device__ __half g_inpH[MTOT*512];
__device__ __half g_AH  [Bb*64*128];
__device__ __half g_w1  [512*256];        // [c][k]
__device__ __half g_wih [768*512];
__device__ __half g_whh [768*256];

// ---------------- helpers ----------------------------------------------------
__device__ __forceinline__ uint32_t smem_u32(const void* p) {
    uint32_t a;
    asm("{ .reg .u64 t; cvta.to.shared.u64 t, %1; cvt.u32.u64 %0, t; }"
        : "=r"(a) : "l"(p));
    return a;
}
__device__ __forceinline__ void cp16(uint32_t dst, const void* src) {
    asm volatile("cp.async.cg.shared.global [%0], [%1], 16;"
                 :: "r"(dst), "l"(src) : "memory");
}
#define CP_COMMIT() asm volatile("cp.async.commit_group;" ::: "memory")
#define CP_WAIT(n)  asm volatile("cp.async.wait_group %0;" :: "n"(n) : "memory")

__device__ __forceinline__ void ldsm_x4(uint32_t& r0, uint32_t& r1,
                                        uint32_t& r2, uint32_t& r3,
                                        uint32_t addr) {
    asm volatile("ldmatrix.sync.aligned.m8n8.x4.shared.b16 {%0,%1,%2,%3}, [%4];"
                 : "=r"(r0), "=r"(r1), "=r"(r2), "=r"(r3) : "r"(addr));
}
__device__ __forceinline__ void ldsm_x4_t(uint32_t& r0, uint32_t& r1,
                                          uint32_t& r2, uint32_t& r3,
                                          uint32_t addr) {
    asm volatile("ldmatrix.sync.aligned.m8n8.x4.trans.shared.b16 {%0,%1,%2,%3}, [%4];"
                 : "=r"(r0), "=r"(r1), "=r"(r2), "=r"(r3) : "r"(addr));
}
__device__ __forceinline__ void mma_f16(float* d,
                                        uint32_t a0, uint32_t a1,
                                        uint32_t a2, uint32_t a3,
                                        uint32_t b0, uint32_t b1) {
    asm volatile(
        "mma.sync.aligned.m16n8k16.row.col.f32.f16.f16.f32 "
        "{%0,%1,%2,%3}, {%4,%5,%6,%7}, {%8,%9}, {%0,%1,%2,%3};"
        : "+f"(d[0]), "+f"(d[1]), "+f"(d[2]), "+f"(d[3])
        : "r"(a0), "r"(a1), "r"(a2), "r"(a3), "r"(b0), "r"(b1));
}

// ---------------- setup -------------------------------------------------------
__global__ void setup_weights(const float* __restrict__ W_in,
                              const float* __restrict__ b_in,
                              const float* __restrict__ W_out,
                              const float* __restrict__ b_out,
                              const float* __restrict__ w_ih,
                              const float* __restrict__ w_hh) {
    int i = blockIdx.x * blockDim.x + threadIdx.x;
    if (i < 512) g_bias1[i] = (i < 256) ? b_in[i] : b_out[i-256];
    if (i < 512*256) {
        int c = i >> 8, k = i & 255;
        float v = (c < 256) ? W_in[c*256 + k] : W_out[(c-256)*256 + k];
        g_w1[i] = __float2half_rn(v);
    }
    if (i < 768*512) g_wih[i] = __float2half_rn(w_ih[i]);
    if (i < 768*256) g_whh[i] = __float2half_rn(w_hh[i]);
}

__global__ void setup_A(const float* __restrict__ A) {
    size_t n = (size_t)Bb*64*128;
    for (size_t i = blockIdx.x*(size_t)blockDim.x + threadIdx.x; i < n;
         i += (size_t)gridDim.x*blockDim.x)
        g_AH[i] = __float2half_rn(A[i]);
}

__global__ void __launch_bounds__(256) init_h(const float* __restrict__ hidden,
                                              const float* __restrict__ mask) {
    int b = blockIdx.x, t = threadIdx.x;
    float len = 0.f, acc = 0.f;
#pragma unroll 4
    for (int n = 0; n < 64; n++) {
        float mk = mask[b*64 + n];
        size_t idx = ((size_t)b*64 + n)*256 + t;
        float v = hidden[idx];
        g_hH[idx] = __float2half_rn(v);
        acc += v * mk; len += mk;
    }
    g_star[(size_t)b*256 + t] = acc / len;
}

// ---------------- FUSED GEMM1+GEMM2 (unchanged from R14) ----------------------
#define F_H    0
#define F_W    33792
#define F_A    74752
#define F_SMEM 83968

__device__ __forceinline__ void f_load_w1(uint32_t sbase, int st, int ch, int half_) {
    const int t = threadIdx.x;
    uint32_t sb = sbase + F_W + st*20480;
#pragma unroll
    for (int f = 0; f < 4; f++) {
        int u = f*256 + t; int row = u >> 2, seg = u & 3;
        cp16(sb + row*80 + seg*16,
             g_w1 + (size_t)(half_*256 + row)*256 + ch*32 + seg*8);
    }
}

__global__ void __launch_bounds__(256, 2) gemm12_mma(const float* __restrict__ b_iah,
                                                     const float* __restrict__ b_oah) {
    extern __shared__ __align__(16) char smem[];
    const int t = threadIdx.x, wid = t >> 5, lane = t & 31;
    const int b = blockIdx.x, half_ = blockIdx.y;
    const int wr = wid >> 2, wc = wid & 3;
    uint32_t sbase = smem_u32(smem);

#pragma unroll
    for (int f = 0; f < 8; f++) {
        int u = f*256 + t; int row = u >> 5, seg = u & 31;
        cp16(sbase + F_H + row*528 + seg*16,
             g_hH + ((size_t)b*64 + row)*256 + seg*8);
    }
#pragma unroll
    for (int f = 0; f < 2; f++) {
        int u = f*256 + t; int row = u >> 3, seg = u & 7;
        cp16(sbase + F_A + row*144 + seg*16,
             g_AH + (size_t)b*8192 + row*128 + half_*64 + seg*8);
    }
    f_load_w1(sbase, 0, 0, half_);
    CP_COMMIT();

    const int midx = lane >> 3;
    const int trow = (midx >> 1)*8 + (lane & 7);
    const int kh   = (midx & 1)*16;

    // ---- phase 1 ----
    {
        float acc[8][2][4];
#pragma unroll
        for (int cf = 0; cf < 8; cf++)
#pragma unroll
            for (int r = 0; r < 2; r++)
#pragma unroll
                for (int i = 0; i < 4; i++) acc[cf][r][i] = 0.f;

        const uint32_t aRow0 = sbase + F_H + (wr*32 + (lane & 15))*528 +
                               (lane >> 4)*16;
        for (int ch = 0; ch < 8; ch++) {
            CP_WAIT(0);
            __syncthreads();
            if (ch + 1 < 8) {
                f_load_w1(sbase, (ch + 1) & 1, ch + 1, half_);
                CP_COMMIT();
            }
            uint32_t sbW = sbase + F_W + (ch & 1)*20480;
#pragma unroll
            for (int kt = 0; kt < 2; kt++) {
                uint32_t a[2][4];
#pragma unroll
                for (int r = 0; r < 2; r++)
                    ldsm_x4(a[r][0], a[r][1], a[r][2], a[r][3],
                            aRow0 + r*16*528 + ch*64 + kt*32);
#pragma unroll
                for (int cf4 = 0; cf4 < 4; cf4++) {
                    uint32_t ba = sbW + (wc*64 + cf4*16 + trow)*80 + kt*32 + kh;
                    uint32_t b0, b1, b2, b3;
                    ldsm_x4(b0, b1, b2, b3, ba);
#pragma unroll
                    for (int r = 0; r < 2; r++) {
                        mma_f16(acc[cf4*2][r],   a[r][0], a[r][1], a[r][2], a[r][3], b0, b1);
                        mma_f16(acc[cf4*2+1][r], a[r][0], a[r][1], a[r][2], a[r][3], b2, b3);
                    }
                }
            }
        }
        __syncthreads();
        const int r0 = wr*32 + (lane >> 2);
        const int cb = (lane & 3)*2;
#pragma unroll
        for (int cf = 0; cf < 8; cf++) {
            int c  = wc*64 + cf*8 + cb;
            float2 bz = *(const float2*)&g_bias1[half_*256 + c];
#pragma unroll
            for (int r = 0; r < 2; r++) {
#pragma unroll
                for (int hrow = 0; hrow < 2; hrow++) {
                    int row = r0 + r*16 + hrow*8;
                    float v0 = acc[cf][r][hrow*2]   + bz.x;
                    float v1 = acc[cf][r][hrow*2+1] + bz.y;
                    *(__half2*)(smem + F_W + row*528 + c*2) =
                        __halves2half2(__float2half_rn(v0), __float2half_rn(v1));
                }
            }
        }
    }
    __syncthreads();

    // ---- phase 2 ----
    {
        float acc[2][8][4];
#pragma unroll
        for (int r = 0; r < 2; r++)
#pragma unroll
            for (int j = 0; j < 8; j++)
#pragma unroll
                for (int i = 0; i < 4; i++) acc[r][j][i] = 0.f;

        uint32_t aBase = sbase + F_A + (wr*32 + (lane & 15))*144 + (lane >> 4)*16;
#pragma unroll
        for (int kt = 0; kt < 4; kt++) {
            uint32_t ah[2][4];
#pragma unroll
            for (int r = 0; r < 2; r++)
                ldsm_x4(ah[r][0], ah[r][1], ah[r][2], ah[r][3],
                        aBase + r*2304 + kt*32);
#pragma unroll
            for (int jj = 0; jj < 4; jj++) {
                uint32_t ba = sbase + F_W + (kt*16 + (lane & 15))*528 +
                              (wc*64 + jj*16 + (lane >> 4)*8)*2;
                uint32_t bh0, bh1, bh2, bh3;
                ldsm_x4_t(bh0, bh1, bh2, bh3, ba);
#pragma unroll
                for (int r = 0; r < 2; r++) {
                    mma_f16(acc[r][jj*2],   ah[r][0], ah[r][1], ah[r][2], ah[r][3], bh0, bh1);
                    mma_f16(acc[r][jj*2+1], ah[r][0], ah[r][1], ah[r][2], ah[r][3], bh2, bh3);
                }
            }
        }
        const float* bias = half_ ? b_oah : b_iah;
#pragma unroll
        for (int r = 0; r < 2; r++) {
            int n = wr*32 + r*16 + (lane >> 2);
#pragma unroll
            for (int j = 0; j < 8; j++) {
                int col = wc*64 + j*8 + (lane & 3)*2;
#pragma unroll
                for (int hrow = 0; hrow < 2; hrow++) {
                    int nn = n + hrow*8;
                    float v0 = acc[r][j][hrow*2]   + bias[col];
                    float v1 = acc[r][j][hrow*2+1] + bias[col+1];
                    size_t o = ((size_t)b*64 + nn)*512 + half_*256 + col;
                    *(__half2*)&g_inpH[o] =
                        __halves2half2(__float2half_rn(v0), __float2half_rn(v1));
                }
            }
        }
    }
}

// ---------------- GEMM3: 32-col CTAs, 3-stage, one sync per chunk --------------
#define G3_B     18432
#define G3_STAGE 32256
#define G3_BIAS  (3*G3_STAGE)     // 96768
#define G3_SMEM  (G3_BIAS + 768)  // 97536

__device__ __forceinline__ void g3_load(uint32_t sbase, int st, int ch,
                                        int m0, int c0) {
    const int t = threadIdx.x;
    uint32_t sb = sbase + st*G3_STAGE;
    const __half *Ah, *Bw; int ak, koff;
    if (ch < 8) { Ah = g_inpH; Bw = g_wih; ak = 512; koff = ch*64; }
    else        { Ah = g_hH;   Bw = g_whh; ak = 256; koff = (ch-8)*64; }
#pragma unroll
    for (int f = 0; f < 4; f++) {
        int u = f*256 + t; int row = u >> 3, seg = u & 7;
        cp16(sb + row*144 + seg*16,
             Ah + (size_t)(m0+row)*ak + koff + seg*8);
    }
#pragma unroll
    for (int f = 0; f < 3; f++) {
        int u = f*256 + t; int row = u >> 3, seg = u & 7;
        int g = row >> 5, n = row & 31;
        cp16(sb + G3_B + row*144 + seg*16,
             Bw + (size_t)(g*256 + c0 + n)*ak + koff + seg*8);
    }
}

template<bool GH>
__device__ __forceinline__ void g3_mma_chunk(uint32_t sb, int wr, int wc, int lane,
                                             float (&acc)[4][2][2][4]) {
    uint32_t aBase = sb + (wr*32 + (lane & 15))*144 + (lane >> 4)*16;
    const int midx = lane >> 3;
    const int trow = (midx >> 1)*8 + (lane & 7);
    const int kh   = (midx & 1)*16;
#pragma unroll
    for (int kt = 0; kt < 4; kt++) {
        uint32_t a[2][4];
#pragma unroll
        for (int r = 0; r < 2; r++)
            ldsm_x4(a[r][0], a[r][1], a[r][2], a[r][3],
                    aBase + r*2304 + kt*32);
#pragma unroll
        for (int g = 0; g < 3; g++) {
            const int p = (!GH || g < 2) ? g : 3;
            uint32_t b0, b1, b2, b3;
            ldsm_x4(b0, b1, b2, b3,
                    sb + G3_B + (g*32 + wc*16 + trow)*144 + kt*32 + kh);
#pragma unroll
            for (int r = 0; r < 2; r++) {
                mma_f16(acc[p][r][0], a[r][0], a[r][1], a[r][2], a[r][3], b0, b1);
                mma_f16(acc[p][r][1], a[r][0], a[r][1], a[r][2], a[r][3], b2, b3);
            }
        }
    }
}

__global__ void __launch_bounds__(256, 2) gemm3_mma(const float* __restrict__ b_ih,
                                                    const float* __restrict__ b_hh) {
    extern __shared__ __align__(16) char smem[];
    const int t = threadIdx.x, wid = t >> 5, lane = t & 31;
    const int c0 = blockIdx.x * 32, m0 = blockIdx.y * 128;
    const int wr = wid & 3, wc = wid >> 2;
    uint32_t sbase = smem_u32(smem);
    float* sbih = (float*)(smem + G3_BIAS);
    float* sbhh = (float*)(smem + G3_BIAS + 384);
    if (t < 32) {
#pragma unroll
        for (int g = 0; g < 3; g++) {
            sbih[g*32 + t] = b_ih[g*256 + c0 + t];
            sbhh[g*32 + t] = b_hh[g*256 + c0 + t];
        }
    }
    float acc[4][2][2][4];
#pragma unroll
    for (int p = 0; p < 4; p++)
#pragma unroll
        for (int r = 0; r < 2; r++)
#pragma unroll
            for (int cgi = 0; cgi < 2; cgi++)
#pragma unroll
                for (int i = 0; i < 4; i++) acc[p][r][cgi][i] = 0.f;

    g3_load(sbase, 0, 0, m0, c0);
    CP_COMMIT();
    g3_load(sbase, 1, 1, m0, c0);
    CP_COMMIT();

    for (int ch = 0; ch < 12; ch++) {
        if (ch < 11) { CP_WAIT(1); } else { CP_WAIT(0); }
        __syncthreads();
        if (ch + 2 < 12) {
            g3_load(sbase, (ch + 2) % 3, ch + 2, m0, c0);
            CP_COMMIT();
        }
        uint32_t sb = sbase + (ch % 3)*G3_STAGE;
        if (ch < 8) g3_mma_chunk<false>(sb, wr, wc, lane, acc);
        else        g3_mma_chunk<true >(sb, wr, wc, lane, acc);
    }

    // GRU epilogue (h from hH)
    const int rbase = m0 + wr*32 + (lane >> 2);
    const int cb = (lane & 3)*2;
#pragma unroll
    for (int r = 0; r < 2; r++) {
#pragma unroll
        for (int cgi = 0; cgi < 2; cgi++) {
            int cl = wc*16 + cgi*8 + cb;
            int c  = c0 + cl;
#pragma unroll
            for (int hrow = 0; hrow < 2; hrow++) {
                int m = rbase + r*16 + hrow*8;
                __half2 hh = *(const __half2*)&g_hH[(size_t)m*256 + c];
                float hv[2] = { __half2float(__low2half(hh)),
                                __half2float(__high2half(hh)) };
                float o[2];
#pragma unroll
                for (int e = 0; e < 2; e++) {
                    int li = cl + e;
                    int fi = hrow*2 + e;
                    float rr = 1.f/(1.f + expf(-(acc[0][r][cgi][fi] +
                                                 sbih[li] + sbhh[li])));
                    float zz = 1.f/(1.f + expf(-(acc[1][r][cgi][fi] +
                                                 sbih[32+li] + sbhh[32+li])));
                    float nn = tanhf(acc[2][r][cgi][fi] + sbih[64+li] +
                                     rr*(acc[3][r][cgi][fi] + sbhh[64+li]));
                    o[e] = nn + zz*(hv[e] - nn);
                }
                *(float2*)&g_hn[(size_t)m*256 + c] = make_float2(o[0], o[1]);
            }
        }
    }
}

// ---------------- attention / star update -------------------------------------
#define ATTN_SMEM ((16384 + 256 + 64 + 64 + 64) * 4)

__global__ void __launch_bounds__(256) attn(const float* __restrict__ mask,
                                            float* __restrict__ out,
                                            int final_) {
    extern __shared__ float sm[];
    float* s_hn    = sm;
    float* s_star  = sm + 16384;
    float* s_alpha = s_star + 256;
    float* s_v     = s_alpha + 64;
    float* s_p     = s_v + 64;
    int b = blockIdx.x, t = threadIdx.x, lane = t & 31, w = t >> 5;
    s_star[t] = g_star[(size_t)b*256 + t];
    const float4* src = (const float4*)&g_hn[(size_t)b*64*256];
    float4* dst = (float4*)s_hn;
#pragma unroll
    for (int f = 0; f < 16; f++) dst[f*256 + t] = src[f*256 + t];
    __syncthreads();
#pragma unroll
    for (int r = 0; r < 8; r++) {
        int n = w*8 + r;
        float p = 0.f;
#pragma unroll
        for (int j = lane; j < 256; j += 32) p += s_hn[n*256 + j] * s_star[j];
#pragma unroll
        for (int o = 16; o; o >>= 1) p += __shfl_xor_sync(0xffffffffu, p, o);
        if (lane == 0) s_v[n] = p;
    }
    __syncthreads();
    float ss = 0.f;
#pragma unroll 8
    for (int j = 0; j < 256; j++) { float x = s_star[j]; ss += x*x; }
    if (t < 64) {
        float sraw = s_v[t];
        float a = 1.f / (1.f + expf(-sraw * 0.0625f));
        s_alpha[t] = a;
        float d2 = (1.f - a)*sraw + a*ss;
        s_v[t] = expf(d2) * mask[(size_t)b*64 + t];
    }
    __syncthreads();
    float den = 1e-24f;
#pragma unroll
    for (int n = 0; n < 64; n++) den += s_v[n];
    if (t < 64) s_p[t] = s_v[t] / den;
    __syncthreads();
    float st = s_star[t];
    float accS = 0.f;
#pragma unroll 4
    for (int n = 0; n < 64; n++) {
        float a = s_alpha[n];
        size_t idx = ((size_t)b*64 + n)*256 + t;
        float h2 = (1.f - a)*s_hn[n*256 + t] + a*st;
        g_hH[idx] = __float2half_rn(h2);
        if (final_) out[idx] = h2;
        accS += s_p[n] * h2;
    }
    g_star[(size_t)b*256 + t] = accS;
    if (final_) out[(size_t)Bb*Nn*Hh + (size_t)b*256 + t] = accS;
}

// ---------------- launch ------------------------------------------------------
extern "C" void kernel_launch(void* const* d_in, const int* in_sizes, int n_in,
                              void* d_out, int out_size) {
    const float* A      = (const float*)d_in[0];
    const float* hidden = (const float*)d_in[1];
    const float* mask   = (const float*)d_in[2];
    const float* w_ih   = (const float*)d_in[3];
    const float* w_hh   = (const float*)d_in[4];
    const float* b_ih   = (const float*)d_in[5];
    const float* b_hh   = (const float*)d_in[6];
    const float* b_iah  = (const float*)d_in[7];
    const float* b_oah  = (const float*)d_in[8];
    const float* W_in   = (const float*)d_in[9];
    const float* b_in   = (const float*)d_in[10];
    const float* W_out  = (const float*)d_in[11];
    const float* b_out  = (const float*)d_in[12];
    float* out = (float*)d_out;

    cudaFuncSetAttribute(gemm12_mma, cudaFuncAttributeMaxDynamicSharedMemorySize, F_SMEM);
    cudaFuncSetAttribute(gemm3_mma,  cudaFuncAttributeMaxDynamicSharedMemorySize, G3_SMEM);
    cudaFuncSetAttribute(attn,       cudaFuncAttributeMaxDynamicSharedMemorySize, ATTN_SMEM);

    setup_weights<<<1536, 256>>>(W_in, b_in, W_out, b_out, w_ih, w_hh);
    setup_A<<<4096, 256>>>(A);
    init_h<<<Bb, 256>>>(hidden, mask);

    for (int s = 0; s < 2; s++) {
        gemm12_mma<<<dim3(Bb, 2), 256, F_SMEM>>>(b_iah, b_oah);
        gemm3_mma<<<dim3(8, 1024), 256, G3_SMEM>>>(b_ih, b_hh);
        attn<<<Bb, 256, ATTN_SMEM>>>(mask, out, s == 1);
    }
}